// round 11
// baseline (speedup 1.0000x reference)
#include <cuda_runtime.h>
#include <cuda_bf16.h>
#include <math.h>
#include <stdint.h>

#define NN 50000
#define EE 800000
#define DD 200
#define KP 208            // padded K / padded N for weights
#define BM 128            // M tile per CTA
#define NTILES ((NN + BM - 1) / BM)   // 391

// smem stage layout for GEMM (bytes)
#define SO_AHI 0
#define SO_ALO 18432
#define SO_BHI 36864
#define SO_BLO 66816
#define STAGE_BYTES 96768
#define SM_TOT (2 * STAGE_BYTES)      // 193536

// ================= device scratch =================
__device__ __align__(128) float g_agg[NN * DD];
__device__ __align__(128) float g_h1[NN * DD];
__device__ __align__(128) float g_norm[NN];      // raw degree counts
__device__ __align__(128) float g_lw2t[DD * DD];
__device__ __align__(128) float g_bfin[DD];
__device__ __align__(128) unsigned long long g_epk[EE];  // (et<<32)|(dst<<16)|src
__device__ __align__(128) __nv_bfloat16 g_xhi[NN * KP],  g_xlo[NN * KP];
__device__ __align__(128) __nv_bfloat16 g_h1hi[NN * KP], g_h1lo[NN * KP];
__device__ __align__(128) __nv_bfloat16 g_a2hi[NN * KP], g_a2lo[NN * KP];
__device__ __align__(128) __nv_bfloat16 g_h0hi[NN * KP], g_h0lo[NN * KP];
__device__ __align__(128) __nv_bfloat16 g_w1hi[KP * KP],  g_w1lo[KP * KP];
__device__ __align__(128) __nv_bfloat16 g_wihhi[KP * KP], g_wihlo[KP * KP];
__device__ __align__(128) __nv_bfloat16 g_whhhi[KP * KP], g_whhlo[KP * KP];
__device__ __align__(128) __nv_bfloat16 g_mthi[KP * KP],  g_mtlo[KP * KP];

// ================= degree + index pack =================
__global__ void deg_kernel(const int* __restrict__ dst) {
    int e = blockIdx.x * blockDim.x + threadIdx.x;
    if (e < EE) atomicAdd(&g_norm[dst[e]], 1.0f);
}

__global__ void pack_kernel(const int* __restrict__ src,
                            const int* __restrict__ dst,
                            const int* __restrict__ et) {
    int e = blockIdx.x * blockDim.x + threadIdx.x;
    if (e >= EE) return;
    g_epk[e] = ((unsigned long long)(unsigned)et[e] << 32) |
               ((unsigned long long)(unsigned)dst[e] << 16) |
               (unsigned long long)(unsigned)src[e];
}

// ================= edge message + scatter (packed indices) =================
__global__ void edge_kernel(const float* __restrict__ x,
                            const float* __restrict__ w) {
    int idx = blockIdx.x * blockDim.x + threadIdx.x;
    if (idx >= EE * 50) return;
    int e  = idx / 50;
    int b2 = idx - e * 50;

    unsigned long long pk = __ldg(&g_epk[e]);
    int s = (int)(pk & 0xffff);
    int d = (int)((pk >> 16) & 0xffff);
    int r = (int)(pk >> 32);

    float4 xv = *(const float4*)(x + (long)s * DD + b2 * 4);
    const float4* wp = (const float4*)(w + (long)r * 400 + b2 * 8);
    float4 wA = wp[0];
    float4 wB = wp[1];

    float o0 = xv.x * wA.x + xv.y * wA.z;
    float o1 = xv.x * wA.y + xv.y * wA.w;
    float o2 = xv.z * wB.x + xv.w * wB.z;
    float o3 = xv.z * wB.y + xv.w * wB.w;

    float* ap = g_agg + (long)d * DD + b2 * 4;
    asm volatile("red.global.add.v4.f32 [%0], {%1, %2, %3, %4};"
                 :: "l"(ap), "f"(o0), "f"(o1), "f"(o2), "f"(o3) : "memory");
}

// ================= hi/lo conversions (vectorized 4x; norm inlined) =================
__global__ void conv_node(const float* __restrict__ src,
                          __nv_bfloat16* __restrict__ hi,
                          __nv_bfloat16* __restrict__ lo, int useNorm) {
    int idx = blockIdx.x * blockDim.x + threadIdx.x;   // NN*52
    if (idx >= NN * 52) return;
    int n = idx / 52;
    int c4 = idx - n * 52;
    float4 v = make_float4(0.f, 0.f, 0.f, 0.f);
    if (c4 < 50) {
        v = *(const float4*)(src + (long)n * DD + c4 * 4);
        if (useNorm) {
            float dcnt = g_norm[n];
            float nv = (dcnt > 0.0f) ? (1.0f / dcnt) : 0.0f;
            v.x *= nv; v.y *= nv; v.z *= nv; v.w *= nv;
        }
    }
    __nv_bfloat16 h0 = __float2bfloat16(v.x);
    __nv_bfloat16 h1 = __float2bfloat16(v.y);
    __nv_bfloat16 h2 = __float2bfloat16(v.z);
    __nv_bfloat16 h3 = __float2bfloat16(v.w);
    __nv_bfloat162 hp0; hp0.x = h0; hp0.y = h1;
    __nv_bfloat162 hp1; hp1.x = h2; hp1.y = h3;
    __nv_bfloat162 lp0;
    lp0.x = __float2bfloat16(v.x - __bfloat162float(h0));
    lp0.y = __float2bfloat16(v.y - __bfloat162float(h1));
    __nv_bfloat162 lp1;
    lp1.x = __float2bfloat16(v.z - __bfloat162float(h2));
    lp1.y = __float2bfloat16(v.w - __bfloat162float(h3));
    long o = (long)n * KP + c4 * 4;
    *(__nv_bfloat162*)(hi + o) = hp0;
    *(__nv_bfloat162*)(hi + o + 2) = hp1;
    *(__nv_bfloat162*)(lo + o) = lp0;
    *(__nv_bfloat162*)(lo + o + 2) = lp1;
}

// zero only pad columns 200..207 of h1hi/h1lo
__global__ void padzero_kernel(__nv_bfloat16* __restrict__ hi,
                               __nv_bfloat16* __restrict__ lo) {
    int idx = blockIdx.x * blockDim.x + threadIdx.x;   // NN
    if (idx >= NN) return;
    uint4 z = make_uint4(0, 0, 0, 0);
    *(uint4*)(hi + (long)idx * KP + DD) = z;
    *(uint4*)(lo + (long)idx * KP + DD) = z;
}

__global__ void conv_weight(const float* __restrict__ src,
                            __nv_bfloat16* __restrict__ hi,
                            __nv_bfloat16* __restrict__ lo, int transpose) {
    int idx = blockIdx.x * blockDim.x + threadIdx.x;
    if (idx >= KP * KP) return;
    int j = idx / KP;
    int c = idx - j * KP;
    float v = 0.0f;
    if (j < DD && c < DD) v = transpose ? src[c * DD + j] : src[j * DD + c];
    __nv_bfloat16 h = __float2bfloat16(v);
    hi[idx] = h;
    lo[idx] = __float2bfloat16(v - __bfloat162float(h));
}

__global__ void tr_lw2(const float* __restrict__ lw2) {
    int idx = blockIdx.x * blockDim.x + threadIdx.x;
    if (idx >= DD * DD) return;
    int t = idx / DD, u = idx - t * DD;
    g_lw2t[u * DD + t] = lw2[idx];
}

__global__ void bmt_kernel(const float* __restrict__ Wih) {
    __shared__ float row[DD];
    int j = blockIdx.x;
    if (j < DD)
        for (int i = threadIdx.x; i < DD; i += 256) row[i] = Wih[j * DD + i];
    __syncthreads();
    int t = threadIdx.x;
    if (t >= KP) return;
    float s = 0.0f;
    if (j < DD && t < DD) {
#pragma unroll 4
        for (int u = 0; u < DD; u++) s += row[u] * g_lw2t[u * DD + t];
    }
    __nv_bfloat16 h = __float2bfloat16(s);
    g_mthi[j * KP + t] = h;
    g_mtlo[j * KP + t] = __float2bfloat16(s - __bfloat162float(h));
}

__global__ void bias_kernel(const float* __restrict__ b2, const float* __restrict__ Wih,
                            const float* __restrict__ bih, const float* __restrict__ bhh) {
    __shared__ float b2s[DD];
    for (int i = threadIdx.x; i < DD; i += 256) b2s[i] = b2[i];
    __syncthreads();
    int j = threadIdx.x;
    if (j >= DD) return;
    float s = bih[j] + bhh[j];
#pragma unroll 4
    for (int t = 0; t < DD; t++) s += b2s[t] * Wih[j * DD + t];
    g_bfin[j] = s;
}

// ================= mma helpers =================
__device__ __forceinline__ uint32_t smem_u32(const void* p) {
    return (uint32_t)__cvta_generic_to_shared(p);
}
__device__ __forceinline__ void ldsm4(uint32_t* r, uint32_t addr) {
    asm volatile("ldmatrix.sync.aligned.m8n8.x4.shared.b16 {%0,%1,%2,%3}, [%4];"
                 : "=r"(r[0]), "=r"(r[1]), "=r"(r[2]), "=r"(r[3]) : "r"(addr));
}
__device__ __forceinline__ void ldsm2(uint32_t* r, uint32_t addr) {
    asm volatile("ldmatrix.sync.aligned.m8n8.x2.shared.b16 {%0,%1}, [%2];"
                 : "=r"(r[0]), "=r"(r[1]) : "r"(addr));
}
__device__ __forceinline__ void mma_bf16(float* c, const uint32_t* a, const uint32_t* b) {
    asm volatile(
        "mma.sync.aligned.m16n8k16.row.col.f32.bf16.bf16.f32 "
        "{%0,%1,%2,%3}, {%4,%5,%6,%7}, {%8,%9}, {%0,%1,%2,%3};"
        : "+f"(c[0]), "+f"(c[1]), "+f"(c[2]), "+f"(c[3])
        : "r"(a[0]), "r"(a[1]), "r"(a[2]), "r"(a[3]), "r"(b[0]), "r"(b[1]));
}
__device__ __forceinline__ void cpa16(uint32_t dsts, const void* src, bool valid) {
    int sz = valid ? 16 : 0;
    asm volatile("cp.async.cg.shared.global [%0], [%1], 16, %2;"
                 :: "r"(dsts), "l"(src), "r"(sz));
}
#define CP_COMMIT() asm volatile("cp.async.commit_group;" ::: "memory")
#define CP_WAIT1()  asm volatile("cp.async.wait_group 1;" ::: "memory")
#define CP_WAIT0()  asm volatile("cp.async.wait_group 0;" ::: "memory")

// ================= pipelined 3-term MMA GEMM (R6-proven core) =================
// HAS_AGG epilogue: inline 1/deg; re-zeros g_agg after read (pre-zeroes layer-2
// accumulation, removing the 40MB memset between mma1 and edge2).
template <int NPASS, bool HAS_AGG, bool WRITE_H1>
__global__ void __launch_bounds__(256, 1) mma_gemm(
    const __nv_bfloat16* __restrict__ A0h, const __nv_bfloat16* __restrict__ A0l,
    const __nv_bfloat16* __restrict__ B0h, const __nv_bfloat16* __restrict__ B0l,
    const __nv_bfloat16* __restrict__ A1h, const __nv_bfloat16* __restrict__ A1l,
    const __nv_bfloat16* __restrict__ B1h, const __nv_bfloat16* __restrict__ B1l,
    const __nv_bfloat16* __restrict__ A2h, const __nv_bfloat16* __restrict__ A2l,
    const __nv_bfloat16* __restrict__ B2h, const __nv_bfloat16* __restrict__ B2l,
    const float* __restrict__ bias, float* __restrict__ outf,
    __nv_bfloat16* __restrict__ h1hi, __nv_bfloat16* __restrict__ h1lo) {
    extern __shared__ __align__(128) char smem[];
    uint32_t sb = smem_u32(smem);

    int tid = threadIdx.x;
    int lane = tid & 31;
    int wid = tid >> 5;
    int wm = wid & 3;
    int wn = wid >> 2;
    int row0 = blockIdx.x * BM;

    float acc[2][13][4];
#pragma unroll
    for (int mi = 0; mi < 2; mi++)
#pragma unroll
        for (int nt = 0; nt < 13; nt++)
#pragma unroll
            for (int q = 0; q < 4; q++) acc[mi][nt][q] = 0.0f;

    const __nv_bfloat16* Ahp[3] = {A0h, A1h, A2h};
    const __nv_bfloat16* Alp[3] = {A0l, A1l, A2l};
    const __nv_bfloat16* Bhp[3] = {B0h, B1h, B2h};
    const __nv_bfloat16* Blp[3] = {B0l, B1l, B2l};

    const int total = NPASS * 4;

    auto load_chunk = [&](int t, int stage) {
        int p = t >> 2, c = t & 3;
        int kb = c * 64;
        int sh = (c == 3) ? 1 : 3;
        int msk = (1 << sh) - 1;
        uint32_t base = sb + stage * STAGE_BYTES;
        const __nv_bfloat16* Ah = Ahp[p];
        const __nv_bfloat16* Al = Alp[p];
        const __nv_bfloat16* Bh = Bhp[p];
        const __nv_bfloat16* Bl = Blp[p];
        int nA = 128 << sh;
        for (int i = tid; i < nA; i += 256) {
            int r = i >> sh, u = i & msk;
            int gr = row0 + r;
            bool v = gr < NN;
            long off = (long)gr * KP + kb + u * 8;
            cpa16(base + SO_AHI + r * 144 + u * 16, Ah + off, v);
            cpa16(base + SO_ALO + r * 144 + u * 16, Al + off, v);
        }
        int nB = 208 << sh;
        for (int i = tid; i < nB; i += 256) {
            int r = i >> sh, u = i & msk;
            long off = (long)r * KP + kb + u * 8;
            cpa16(base + SO_BHI + r * 144 + u * 16, Bh + off, true);
            cpa16(base + SO_BLO + r * 144 + u * 16, Bl + off, true);
        }
        CP_COMMIT();
    };

    uint32_t a_off = (uint32_t)((wm * 32 + (lane & 15)) * 144 + (((lane >> 4) << 3) << 1));
    uint32_t b_off = (uint32_t)((wn * 104 + (lane & 7) + ((lane >> 4) << 3)) * 144 +
                                ((((lane >> 3) & 1) << 3) << 1));
    uint32_t b2_off = (uint32_t)((wn * 104 + 96 + (lane & 7)) * 144 +
                                 ((((lane >> 3) & 1) << 3) << 1));

    load_chunk(0, 0);

#pragma unroll 1
    for (int t = 0; t < total; t++) {
        if (t + 1 < total) {
            load_chunk(t + 1, (t + 1) & 1);
            CP_WAIT1();
        } else {
            CP_WAIT0();
        }
        __syncthreads();

        int c = t & 3;
        int nk16 = (c == 3) ? 1 : 4;
        uint32_t base = sb + (t & 1) * STAGE_BYTES;
#pragma unroll
        for (int k16 = 0; k16 < 4; k16++) {
            if (k16 >= nk16) break;
            uint32_t kofs = (uint32_t)(k16 << 5);
            uint32_t ah[2][4], al[2][4];
#pragma unroll
            for (int mi = 0; mi < 2; mi++) {
                ldsm4(ah[mi], base + SO_AHI + a_off + mi * (16 * 144) + kofs);
                ldsm4(al[mi], base + SO_ALO + a_off + mi * (16 * 144) + kofs);
            }
#pragma unroll
            for (int bt = 0; bt < 6; bt++) {
                uint32_t bh[4], bl[4];
                ldsm4(bh, base + SO_BHI + b_off + bt * (16 * 144) + kofs);
                ldsm4(bl, base + SO_BLO + b_off + bt * (16 * 144) + kofs);
#pragma unroll
                for (int mi = 0; mi < 2; mi++) {
                    mma_bf16(acc[mi][2 * bt],     ah[mi], bh);
                    mma_bf16(acc[mi][2 * bt + 1], ah[mi], bh + 2);
                    mma_bf16(acc[mi][2 * bt],     ah[mi], bl);
                    mma_bf16(acc[mi][2 * bt + 1], ah[mi], bl + 2);
                    mma_bf16(acc[mi][2 * bt],     al[mi], bh);
                    mma_bf16(acc[mi][2 * bt + 1], al[mi], bh + 2);
                }
            }
            {
                uint32_t bh[2], bl[2];
                ldsm2(bh, base + SO_BHI + b2_off + kofs);
                ldsm2(bl, base + SO_BLO + b2_off + kofs);
#pragma unroll
                for (int mi = 0; mi < 2; mi++) {
                    mma_bf16(acc[mi][12], ah[mi], bh);
                    mma_bf16(acc[mi][12], ah[mi], bl);
                    mma_bf16(acc[mi][12], al[mi], bh);
                }
            }
        }
        __syncthreads();
    }

    // ---- epilogue ----
#pragma unroll
    for (int mi = 0; mi < 2; mi++) {
        int r0 = row0 + wm * 32 + mi * 16 + (lane >> 2);
#pragma unroll
        for (int half = 0; half < 2; half++) {
            int gr = r0 + half * 8;
            if (gr >= NN) continue;
            float nv = 0.0f;
            if (HAS_AGG) {
                float dcnt = g_norm[gr];
                nv = (dcnt > 0.0f) ? (1.0f / dcnt) : 0.0f;
            }
#pragma unroll
            for (int nt = 0; nt < 13; nt++) {
                int col = wn * 104 + nt * 8 + ((lane & 3) << 1);
                if (col >= DD) continue;
                float v0 = acc[mi][nt][half * 2 + 0];
                float v1 = acc[mi][nt][half * 2 + 1];
                if (HAS_AGG) {
                    float2 ag = *(const float2*)(g_agg + (long)gr * DD + col);
                    v0 += ag.x * nv;
                    v1 += ag.y * nv;
                    // re-zero for layer-2 accumulation (replaces 40MB memset)
                    *(float2*)(g_agg + (long)gr * DD + col) = make_float2(0.0f, 0.0f);
                }
                float2 bb = *(const float2*)(bias + col);
                v0 = tanhf(v0 + bb.x);
                v1 = tanhf(v1 + bb.y);
                *(float2*)(outf + (long)gr * DD + col) = make_float2(v0, v1);
                if (WRITE_H1) {
                    __nv_bfloat16 h0b = __float2bfloat16(v0);
                    __nv_bfloat16 h1b = __float2bfloat16(v1);
                    __nv_bfloat162 hp; hp.x = h0b; hp.y = h1b;
                    __nv_bfloat162 lp;
                    lp.x = __float2bfloat16(v0 - __bfloat162float(h0b));
                    lp.y = __float2bfloat16(v1 - __bfloat162float(h1b));
                    *(__nv_bfloat162*)(h1hi + (long)gr * KP + col) = hp;
                    *(__nv_bfloat162*)(h1lo + (long)gr * KP + col) = lp;
                }
            }
        }
    }
}

// ================= launch =================
extern "C" void kernel_launch(void* const* d_in, const int* in_sizes, int n_in,
                              void* d_out, int out_size) {
    const float* node_feat = (const float*)d_in[0];
    const float* dyn       = (const float*)d_in[1];
    const int*   src       = (const int*)d_in[2];
    const int*   dst       = (const int*)d_in[3];
    const int*   et        = (const int*)d_in[4];
    const float* w1        = (const float*)d_in[5];
    const float* lw1       = (const float*)d_in[6];
    const float* b1        = (const float*)d_in[7];
    const float* w2        = (const float*)d_in[8];
    const float* lw2       = (const float*)d_in[9];
    const float* b2        = (const float*)d_in[10];
    const float* Wih       = (const float*)d_in[11];
    const float* Whh       = (const float*)d_in[12];
    const float* bih       = (const float*)d_in[13];
    const float* bhh       = (const float*)d_in[14];
    float* out = (float*)d_out;

    void *agg_p, *norm_p, *h1_p, *bfin_p;
    void *xhi, *xlo, *h1hi, *h1lo, *a2hi, *a2lo, *h0hi, *h0lo;
    void *w1hi, *w1lo, *wihhi, *wihlo, *whhhi, *whhlo, *mthi, *mtlo;
    cudaGetSymbolAddress(&agg_p, g_agg);
    cudaGetSymbolAddress(&norm_p, g_norm);
    cudaGetSymbolAddress(&h1_p, g_h1);
    cudaGetSymbolAddress(&bfin_p, g_bfin);
    cudaGetSymbolAddress(&xhi, g_xhi);     cudaGetSymbolAddress(&xlo, g_xlo);
    cudaGetSymbolAddress(&h1hi, g_h1hi);   cudaGetSymbolAddress(&h1lo, g_h1lo);
    cudaGetSymbolAddress(&a2hi, g_a2hi);   cudaGetSymbolAddress(&a2lo, g_a2lo);
    cudaGetSymbolAddress(&h0hi, g_h0hi);   cudaGetSymbolAddress(&h0lo, g_h0lo);
    cudaGetSymbolAddress(&w1hi, g_w1hi);   cudaGetSymbolAddress(&w1lo, g_w1lo);
    cudaGetSymbolAddress(&wihhi, g_wihhi); cudaGetSymbolAddress(&wihlo, g_wihlo);
    cudaGetSymbolAddress(&whhhi, g_whhhi); cudaGetSymbolAddress(&whhlo, g_whhlo);
    cudaGetSymbolAddress(&mthi, g_mthi);   cudaGetSymbolAddress(&mtlo, g_mtlo);

    cudaFuncSetAttribute(mma_gemm<1, true, true>,
                         cudaFuncAttributeMaxDynamicSharedMemorySize, SM_TOT);
    cudaFuncSetAttribute(mma_gemm<3, false, false>,
                         cudaFuncAttributeMaxDynamicSharedMemorySize, SM_TOT);

    cudaMemsetAsync(agg_p, 0, sizeof(float) * NN * DD);
    cudaMemsetAsync(norm_p, 0, sizeof(float) * NN);

    deg_kernel<<<(EE + 255) / 256, 256>>>(dst);
    pack_kernel<<<(EE + 255) / 256, 256>>>(src, dst, et);

    conv_weight<<<(KP * KP + 255) / 256, 256>>>(lw1, (__nv_bfloat16*)w1hi, (__nv_bfloat16*)w1lo, 1);
    conv_weight<<<(KP * KP + 255) / 256, 256>>>(Wih, (__nv_bfloat16*)wihhi, (__nv_bfloat16*)wihlo, 0);
    conv_weight<<<(KP * KP + 255) / 256, 256>>>(Whh, (__nv_bfloat16*)whhhi, (__nv_bfloat16*)whhlo, 0);
    tr_lw2<<<(DD * DD + 255) / 256, 256>>>(lw2);
    bmt_kernel<<<KP, 256>>>(Wih);
    bias_kernel<<<1, 256>>>(b2, Wih, bih, bhh);
    padzero_kernel<<<(NN + 255) / 256, 256>>>((__nv_bfloat16*)h1hi, (__nv_bfloat16*)h1lo);

    const int ncv = (NN * 52 + 255) / 256;
    conv_node<<<ncv, 256>>>(node_feat, (__nv_bfloat16*)xhi, (__nv_bfloat16*)xlo, 0);
    conv_node<<<ncv, 256>>>(dyn, (__nv_bfloat16*)h0hi, (__nv_bfloat16*)h0lo, 0);

    // layer 1
    edge_kernel<<<(EE * 50 + 255) / 256, 256>>>(node_feat, w1);
    mma_gemm<1, true, true><<<NTILES, 256, SM_TOT>>>(
        (const __nv_bfloat16*)xhi, (const __nv_bfloat16*)xlo,
        (const __nv_bfloat16*)w1hi, (const __nv_bfloat16*)w1lo,
        nullptr, nullptr, nullptr, nullptr,
        nullptr, nullptr, nullptr, nullptr,
        b1, (float*)h1_p, (__nv_bfloat16*)h1hi, (__nv_bfloat16*)h1lo);

    // layer 2 scatter (g_agg pre-zeroed by mma1 epilogue) + convert
    edge_kernel<<<(EE * 50 + 255) / 256, 256>>>((const float*)h1_p, w2);
    conv_node<<<ncv, 256>>>((const float*)agg_p, (__nv_bfloat16*)a2hi, (__nv_bfloat16*)a2lo, 1);

    // fused final: out = tanh( agg2n@Wih^T + h1@(lw2@Wih^T) + h0@Whh^T + bfin )
    mma_gemm<3, false, false><<<NTILES, 256, SM_TOT>>>(
        (const __nv_bfloat16*)a2hi, (const __nv_bfloat16*)a2lo,
        (const __nv_bfloat16*)wihhi, (const __nv_bfloat16*)wihlo,
        (const __nv_bfloat16*)h1hi, (const __nv_bfloat16*)h1lo,
        (const __nv_bfloat16*)mthi, (const __nv_bfloat16*)mtlo,
        (const __nv_bfloat16*)h0hi, (const __nv_bfloat16*)h0lo,
        (const __nv_bfloat16*)whhhi, (const __nv_bfloat16*)whhlo,
        (const float*)bfin_p, out, nullptr, nullptr);
}

// round 12
// speedup vs baseline: 1.6081x; 1.6081x over previous
#include <cuda_runtime.h>
#include <cuda_bf16.h>
#include <math.h>
#include <stdint.h>

#define NN 50000
#define EE 800000
#define DD 200
#define KP 208            // padded K / padded N for weights
#define BM 128            // M tile per CTA
#define NTILES ((NN + BM - 1) / BM)   // 391

// smem stage layout for GEMM (bytes); K-chunk = 32 cols, row stride 80B
#define SO_AHI 0
#define SO_ALO 10240
#define SO_BHI 20480
#define SO_BLO 37120
#define STAGE_BYTES 53760
#define NSTAGE 4
#define SM_TOT (NSTAGE * STAGE_BYTES)   // 215040

// ================= device scratch =================
__device__ __align__(128) float g_agg[NN * DD];
__device__ __align__(128) float g_h1[NN * DD];
__device__ __align__(128) float g_norm[NN];
__device__ __align__(128) float g_lw2t[DD * DD];
__device__ __align__(128) float g_bfin[DD];
__device__ __align__(128) __nv_bfloat16 g_xhi[NN * KP],  g_xlo[NN * KP];
__device__ __align__(128) __nv_bfloat16 g_h1hi[NN * KP], g_h1lo[NN * KP];
__device__ __align__(128) __nv_bfloat16 g_a2hi[NN * KP], g_a2lo[NN * KP];
__device__ __align__(128) __nv_bfloat16 g_h0hi[NN * KP], g_h0lo[NN * KP];
__device__ __align__(128) __nv_bfloat16 g_w1hi[KP * KP],  g_w1lo[KP * KP];
__device__ __align__(128) __nv_bfloat16 g_wihhi[KP * KP], g_wihlo[KP * KP];
__device__ __align__(128) __nv_bfloat16 g_whhhi[KP * KP], g_whhlo[KP * KP];
__device__ __align__(128) __nv_bfloat16 g_mthi[KP * KP],  g_mtlo[KP * KP];

// ================= degree / norm =================
__global__ void deg_kernel(const int* __restrict__ dst) {
    int e = blockIdx.x * blockDim.x + threadIdx.x;
    if (e < EE) atomicAdd(&g_norm[dst[e]], 1.0f);
}
__global__ void norm_kernel() {
    int n = blockIdx.x * blockDim.x + threadIdx.x;
    if (n < NN) {
        float d = g_norm[n];
        g_norm[n] = (d > 0.0f) ? (1.0f / d) : 0.0f;
    }
}

// ================= edge message + scatter (R1/R6-proven) =================
__global__ void edge_kernel(const float* __restrict__ x,
                            const int* __restrict__ src,
                            const int* __restrict__ dst,
                            const int* __restrict__ et,
                            const float* __restrict__ w) {
    int idx = blockIdx.x * blockDim.x + threadIdx.x;
    if (idx >= EE * 50) return;
    int e  = idx / 50;
    int b2 = idx - e * 50;

    int s = __ldg(&src[e]);
    int d = __ldg(&dst[e]);
    int r = __ldg(&et[e]);

    float4 xv = *(const float4*)(x + (long)s * DD + b2 * 4);
    const float4* wp = (const float4*)(w + (long)r * 400 + b2 * 8);
    float4 wA = wp[0];
    float4 wB = wp[1];

    float o0 = xv.x * wA.x + xv.y * wA.z;
    float o1 = xv.x * wA.y + xv.y * wA.w;
    float o2 = xv.z * wB.x + xv.w * wB.z;
    float o3 = xv.z * wB.y + xv.w * wB.w;

    float* ap = g_agg + (long)d * DD + b2 * 4;
    asm volatile("red.global.add.v4.f32 [%0], {%1, %2, %3, %4};"
                 :: "l"(ap), "f"(o0), "f"(o1), "f"(o2), "f"(o3) : "memory");
}

// ================= hi/lo conversions (vectorized 4x) =================
__global__ void conv_node(const float* __restrict__ src,
                          __nv_bfloat16* __restrict__ hi,
                          __nv_bfloat16* __restrict__ lo, int useNorm) {
    int idx = blockIdx.x * blockDim.x + threadIdx.x;   // NN*52
    if (idx >= NN * 52) return;
    int n = idx / 52;
    int c4 = idx - n * 52;
    float4 v = make_float4(0.f, 0.f, 0.f, 0.f);
    if (c4 < 50) {
        v = *(const float4*)(src + (long)n * DD + c4 * 4);
        if (useNorm) {
            float nv = g_norm[n];
            v.x *= nv; v.y *= nv; v.z *= nv; v.w *= nv;
        }
    }
    __nv_bfloat16 h0 = __float2bfloat16(v.x);
    __nv_bfloat16 h1 = __float2bfloat16(v.y);
    __nv_bfloat16 h2 = __float2bfloat16(v.z);
    __nv_bfloat16 h3 = __float2bfloat16(v.w);
    __nv_bfloat162 hp0; hp0.x = h0; hp0.y = h1;
    __nv_bfloat162 hp1; hp1.x = h2; hp1.y = h3;
    __nv_bfloat162 lp0;
    lp0.x = __float2bfloat16(v.x - __bfloat162float(h0));
    lp0.y = __float2bfloat16(v.y - __bfloat162float(h1));
    __nv_bfloat162 lp1;
    lp1.x = __float2bfloat16(v.z - __bfloat162float(h2));
    lp1.y = __float2bfloat16(v.w - __bfloat162float(h3));
    long o = (long)n * KP + c4 * 4;
    *(__nv_bfloat162*)(hi + o) = hp0;
    *(__nv_bfloat162*)(hi + o + 2) = hp1;
    *(__nv_bfloat162*)(lo + o) = lp0;
    *(__nv_bfloat162*)(lo + o + 2) = lp1;
}

// zero only pad columns 200..207 of h1hi/h1lo
__global__ void padzero_kernel(__nv_bfloat16* __restrict__ hi,
                               __nv_bfloat16* __restrict__ lo) {
    int idx = blockIdx.x * blockDim.x + threadIdx.x;   // NN
    if (idx >= NN) return;
    uint4 z = make_uint4(0, 0, 0, 0);
    *(uint4*)(hi + (long)idx * KP + DD) = z;
    *(uint4*)(lo + (long)idx * KP + DD) = z;
}

__global__ void conv_weight(const float* __restrict__ src,
                            __nv_bfloat16* __restrict__ hi,
                            __nv_bfloat16* __restrict__ lo, int transpose) {
    int idx = blockIdx.x * blockDim.x + threadIdx.x;
    if (idx >= KP * KP) return;
    int j = idx / KP;
    int c = idx - j * KP;
    float v = 0.0f;
    if (j < DD && c < DD) v = transpose ? src[c * DD + j] : src[j * DD + c];
    __nv_bfloat16 h = __float2bfloat16(v);
    hi[idx] = h;
    lo[idx] = __float2bfloat16(v - __bfloat162float(h));
}

__global__ void tr_lw2(const float* __restrict__ lw2) {
    int idx = blockIdx.x * blockDim.x + threadIdx.x;
    if (idx >= DD * DD) return;
    int t = idx / DD, u = idx - t * DD;
    g_lw2t[u * DD + t] = lw2[idx];
}

__global__ void bmt_kernel(const float* __restrict__ Wih) {
    __shared__ float row[DD];
    int j = blockIdx.x;
    if (j < DD)
        for (int i = threadIdx.x; i < DD; i += 256) row[i] = Wih[j * DD + i];
    __syncthreads();
    int t = threadIdx.x;
    if (t >= KP) return;
    float s = 0.0f;
    if (j < DD && t < DD) {
#pragma unroll 4
        for (int u = 0; u < DD; u++) s += row[u] * g_lw2t[u * DD + t];
    }
    __nv_bfloat16 h = __float2bfloat16(s);
    g_mthi[j * KP + t] = h;
    g_mtlo[j * KP + t] = __float2bfloat16(s - __bfloat162float(h));
}

__global__ void bias_kernel(const float* __restrict__ b2, const float* __restrict__ Wih,
                            const float* __restrict__ bih, const float* __restrict__ bhh) {
    __shared__ float b2s[DD];
    for (int i = threadIdx.x; i < DD; i += 256) b2s[i] = b2[i];
    __syncthreads();
    int j = threadIdx.x;
    if (j >= DD) return;
    float s = bih[j] + bhh[j];
#pragma unroll 4
    for (int t = 0; t < DD; t++) s += b2s[t] * Wih[j * DD + t];
    g_bfin[j] = s;
}

// ================= mma helpers =================
__device__ __forceinline__ uint32_t smem_u32(const void* p) {
    return (uint32_t)__cvta_generic_to_shared(p);
}
__device__ __forceinline__ void ldsm4(uint32_t* r, uint32_t addr) {
    asm volatile("ldmatrix.sync.aligned.m8n8.x4.shared.b16 {%0,%1,%2,%3}, [%4];"
                 : "=r"(r[0]), "=r"(r[1]), "=r"(r[2]), "=r"(r[3]) : "r"(addr));
}
__device__ __forceinline__ void ldsm2(uint32_t* r, uint32_t addr) {
    asm volatile("ldmatrix.sync.aligned.m8n8.x2.shared.b16 {%0,%1}, [%2];"
                 : "=r"(r[0]), "=r"(r[1]) : "r"(addr));
}
__device__ __forceinline__ void mma_bf16(float* c, const uint32_t* a, const uint32_t* b) {
    asm volatile(
        "mma.sync.aligned.m16n8k16.row.col.f32.bf16.bf16.f32 "
        "{%0,%1,%2,%3}, {%4,%5,%6,%7}, {%8,%9}, {%0,%1,%2,%3};"
        : "+f"(c[0]), "+f"(c[1]), "+f"(c[2]), "+f"(c[3])
        : "r"(a[0]), "r"(a[1]), "r"(a[2]), "r"(a[3]), "r"(b[0]), "r"(b[1]));
}
__device__ __forceinline__ void cpa16(uint32_t dsts, const void* src, bool valid) {
    int sz = valid ? 16 : 0;
    asm volatile("cp.async.cg.shared.global [%0], [%1], 16, %2;"
                 :: "r"(dsts), "l"(src), "r"(sz));
}
#define CP_COMMIT() asm volatile("cp.async.commit_group;" ::: "memory")
__device__ __forceinline__ void cp_wait_n(int pend) {
    switch (pend) {
        case 0: asm volatile("cp.async.wait_group 0;" ::: "memory"); break;
        case 1: asm volatile("cp.async.wait_group 1;" ::: "memory"); break;
        case 2: asm volatile("cp.async.wait_group 2;" ::: "memory"); break;
        default: asm volatile("cp.async.wait_group 3;" ::: "memory"); break;
    }
}

// ================= 4-stage pipelined 3-term MMA GEMM (K-chunk = 32) =================
// C[128 x 200] per CTA: C = sum_p (AhiBhi + AhiBlo + AloBhi)_p
// 8 warps 4(M)x2(N); warp 32x104. Chunks per pass: 7 ({32x6, 16}).
template <int NPASS, bool HAS_AGG, bool WRITE_H1>
__global__ void __launch_bounds__(256, 1) mma_gemm(
    const __nv_bfloat16* __restrict__ A0h, const __nv_bfloat16* __restrict__ A0l,
    const __nv_bfloat16* __restrict__ B0h, const __nv_bfloat16* __restrict__ B0l,
    const __nv_bfloat16* __restrict__ A1h, const __nv_bfloat16* __restrict__ A1l,
    const __nv_bfloat16* __restrict__ B1h, const __nv_bfloat16* __restrict__ B1l,
    const __nv_bfloat16* __restrict__ A2h, const __nv_bfloat16* __restrict__ A2l,
    const __nv_bfloat16* __restrict__ B2h, const __nv_bfloat16* __restrict__ B2l,
    const float* __restrict__ bias, float* __restrict__ outf,
    __nv_bfloat16* __restrict__ h1hi, __nv_bfloat16* __restrict__ h1lo) {
    extern __shared__ __align__(128) char smem[];
    uint32_t sb = smem_u32(smem);

    int tid = threadIdx.x;
    int lane = tid & 31;
    int wid = tid >> 5;
    int wm = wid & 3;
    int wn = wid >> 2;
    int row0 = blockIdx.x * BM;

    float acc[2][13][4];
#pragma unroll
    for (int mi = 0; mi < 2; mi++)
#pragma unroll
        for (int nt = 0; nt < 13; nt++)
#pragma unroll
            for (int q = 0; q < 4; q++) acc[mi][nt][q] = 0.0f;

    const __nv_bfloat16* Ahp[3] = {A0h, A1h, A2h};
    const __nv_bfloat16* Alp[3] = {A0l, A1l, A2l};
    const __nv_bfloat16* Bhp[3] = {B0h, B1h, B2h};
    const __nv_bfloat16* Blp[3] = {B0l, B1l, B2l};

    const int total = NPASS * 7;

    // ---- chunk loader (cp.async); chunk c<6: 32 cols, c==6: 16 cols ----
    auto load_chunk = [&](int t, int stage) {
        int p = t / 7, c = t - p * 7;
        int kb = c * 32;
        int sh = (c == 6) ? 1 : 2;          // uint4 per row = 1<<sh
        int msk = (1 << sh) - 1;
        uint32_t base = sb + stage * STAGE_BYTES;
        const __nv_bfloat16* Ah = Ahp[p];
        const __nv_bfloat16* Al = Alp[p];
        const __nv_bfloat16* Bh = Bhp[p];
        const __nv_bfloat16* Bl = Blp[p];
        int nA = 128 << sh;
        for (int i = tid; i < nA; i += 256) {
            int r = i >> sh, u = i & msk;
            int gr = row0 + r;
            bool v = gr < NN;
            long off = (long)gr * KP + kb + u * 8;
            cpa16(base + SO_AHI + r * 80 + u * 16, Ah + off, v);
            cpa16(base + SO_ALO + r * 80 + u * 16, Al + off, v);
        }
        int nB = 208 << sh;
        for (int i = tid; i < nB; i += 256) {
            int r = i >> sh, u = i & msk;
            long off = (long)r * KP + kb + u * 8;
            cpa16(base + SO_BHI + r * 80 + u * 16, Bh + off, true);
            cpa16(base + SO_BLO + r * 80 + u * 16, Bl + off, true);
        }
        CP_COMMIT();
    };

    // per-lane fragment byte offsets within a stage (row stride 80B)
    uint32_t a_off = (uint32_t)((wm * 32 + (lane & 15)) * 80 + (((lane >> 4) << 3) << 1));
    uint32_t b_off = (uint32_t)((wn * 104 + (lane & 7) + ((lane >> 4) << 3)) * 80 +
                                ((((lane >> 3) & 1) << 3) << 1));
    uint32_t b2_off = (uint32_t)((wn * 104 + 96 + (lane & 7)) * 80 +
                                 ((((lane >> 3) & 1) << 3) << 1));

    // prologue: fill 3 stages
    load_chunk(0, 0);
    if (total > 1) load_chunk(1, 1);
    if (total > 2) load_chunk(2, 2);

#pragma unroll 1
    for (int t = 0; t < total; t++) {
        int nt3 = t + 3;
        if (nt3 < total) load_chunk(nt3, nt3 & 3);
        int pend = total - 1 - t;
        if (pend > 3) pend = 3;
        cp_wait_n(pend);
        __syncthreads();

        int c = t - (t / 7) * 7;
        int nk16 = (c == 6) ? 1 : 2;
        uint32_t base = sb + (t & 3) * STAGE_BYTES;
#pragma unroll
        for (int k16 = 0; k16 < 2; k16++) {
            if (k16 >= nk16) break;
            uint32_t kofs = (uint32_t)(k16 << 5);   // 16 bf16 = 32 bytes
            uint32_t ah[2][4], al[2][4];
#pragma unroll
            for (int mi = 0; mi < 2; mi++) {
                ldsm4(ah[mi], base + SO_AHI + a_off + mi * (16 * 80) + kofs);
                ldsm4(al[mi], base + SO_ALO + a_off + mi * (16 * 80) + kofs);
            }
#pragma unroll
            for (int bt = 0; bt < 6; bt++) {
                uint32_t bh[4], bl[4];
                ldsm4(bh, base + SO_BHI + b_off + bt * (16 * 80) + kofs);
                ldsm4(bl, base + SO_BLO + b_off + bt * (16 * 80) + kofs);
#pragma unroll
                for (int mi = 0; mi < 2; mi++) {
                    mma_bf16(acc[mi][2 * bt],     ah[mi], bh);
                    mma_bf16(acc[mi][2 * bt + 1], ah[mi], bh + 2);
                    mma_bf16(acc[mi][2 * bt],     ah[mi], bl);
                    mma_bf16(acc[mi][2 * bt + 1], ah[mi], bl + 2);
                    mma_bf16(acc[mi][2 * bt],     al[mi], bh);
                    mma_bf16(acc[mi][2 * bt + 1], al[mi], bh + 2);
                }
            }
            {
                uint32_t bh[2], bl[2];
                ldsm2(bh, base + SO_BHI + b2_off + kofs);
                ldsm2(bl, base + SO_BLO + b2_off + kofs);
#pragma unroll
                for (int mi = 0; mi < 2; mi++) {
                    mma_bf16(acc[mi][12], ah[mi], bh);
                    mma_bf16(acc[mi][12], ah[mi], bl);
                    mma_bf16(acc[mi][12], al[mi], bh);
                }
            }
        }
        __syncthreads();
    }

    // ---- epilogue ----
#pragma unroll
    for (int mi = 0; mi < 2; mi++) {
        int r0 = row0 + wm * 32 + mi * 16 + (lane >> 2);
#pragma unroll
        for (int half = 0; half < 2; half++) {
            int gr = r0 + half * 8;
            if (gr >= NN) continue;
            float nv = HAS_AGG ? g_norm[gr] : 0.0f;
#pragma unroll
            for (int nt = 0; nt < 13; nt++) {
                int col = wn * 104 + nt * 8 + ((lane & 3) << 1);
                if (col >= DD) continue;
                float v0 = acc[mi][nt][half * 2 + 0];
                float v1 = acc[mi][nt][half * 2 + 1];
                if (HAS_AGG) {
                    float2 ag = *(const float2*)(g_agg + (long)gr * DD + col);
                    v0 += ag.x * nv;
                    v1 += ag.y * nv;
                }
                float2 bb = *(const float2*)(bias + col);
                v0 = tanhf(v0 + bb.x);
                v1 = tanhf(v1 + bb.y);
                *(float2*)(outf + (long)gr * DD + col) = make_float2(v0, v1);
                if (WRITE_H1) {
                    __nv_bfloat16 h0b = __float2bfloat16(v0);
                    __nv_bfloat16 h1b = __float2bfloat16(v1);
                    __nv_bfloat162 hp; hp.x = h0b; hp.y = h1b;
                    __nv_bfloat162 lp;
                    lp.x = __float2bfloat16(v0 - __bfloat162float(h0b));
                    lp.y = __float2bfloat16(v1 - __bfloat162float(h1b));
                    *(__nv_bfloat162*)(h1hi + (long)gr * KP + col) = hp;
                    *(__nv_bfloat162*)(h1lo + (long)gr * KP + col) = lp;
                }
            }
        }
    }
}

// ================= launch =================
extern "C" void kernel_launch(void* const* d_in, const int* in_sizes, int n_in,
                              void* d_out, int out_size) {
    const float* node_feat = (const float*)d_in[0];
    const float* dyn       = (const float*)d_in[1];
    const int*   src       = (const int*)d_in[2];
    const int*   dst       = (const int*)d_in[3];
    const int*   et        = (const int*)d_in[4];
    const float* w1        = (const float*)d_in[5];
    const float* lw1       = (const float*)d_in[6];
    const float* b1        = (const float*)d_in[7];
    const float* w2        = (const float*)d_in[8];
    const float* lw2       = (const float*)d_in[9];
    const float* b2        = (const float*)d_in[10];
    const float* Wih       = (const float*)d_in[11];
    const float* Whh       = (const float*)d_in[12];
    const float* bih       = (const float*)d_in[13];
    const float* bhh       = (const float*)d_in[14];
    float* out = (float*)d_out;

    void *agg_p, *norm_p, *h1_p, *bfin_p;
    void *xhi, *xlo, *h1hi, *h1lo, *a2hi, *a2lo, *h0hi, *h0lo;
    void *w1hi, *w1lo, *wihhi, *wihlo, *whhhi, *whhlo, *mthi, *mtlo;
    cudaGetSymbolAddress(&agg_p, g_agg);
    cudaGetSymbolAddress(&norm_p, g_norm);
    cudaGetSymbolAddress(&h1_p, g_h1);
    cudaGetSymbolAddress(&bfin_p, g_bfin);
    cudaGetSymbolAddress(&xhi, g_xhi);     cudaGetSymbolAddress(&xlo, g_xlo);
    cudaGetSymbolAddress(&h1hi, g_h1hi);   cudaGetSymbolAddress(&h1lo, g_h1lo);
    cudaGetSymbolAddress(&a2hi, g_a2hi);   cudaGetSymbolAddress(&a2lo, g_a2lo);
    cudaGetSymbolAddress(&h0hi, g_h0hi);   cudaGetSymbolAddress(&h0lo, g_h0lo);
    cudaGetSymbolAddress(&w1hi, g_w1hi);   cudaGetSymbolAddress(&w1lo, g_w1lo);
    cudaGetSymbolAddress(&wihhi, g_wihhi); cudaGetSymbolAddress(&wihlo, g_wihlo);
    cudaGetSymbolAddress(&whhhi, g_whhhi); cudaGetSymbolAddress(&whhlo, g_whhlo);
    cudaGetSymbolAddress(&mthi, g_mthi);   cudaGetSymbolAddress(&mtlo, g_mtlo);

    cudaFuncSetAttribute(mma_gemm<1, true, true>,
                         cudaFuncAttributeMaxDynamicSharedMemorySize, SM_TOT);
    cudaFuncSetAttribute(mma_gemm<3, false, false>,
                         cudaFuncAttributeMaxDynamicSharedMemorySize, SM_TOT);

    cudaMemsetAsync(agg_p, 0, sizeof(float) * NN * DD);
    cudaMemsetAsync(norm_p, 0, sizeof(float) * NN);

    deg_kernel<<<(EE + 255) / 256, 256>>>(dst);
    norm_kernel<<<(NN + 255) / 256, 256>>>();

    conv_weight<<<(KP * KP + 255) / 256, 256>>>(lw1, (__nv_bfloat16*)w1hi, (__nv_bfloat16*)w1lo, 1);
    conv_weight<<<(KP * KP + 255) / 256, 256>>>(Wih, (__nv_bfloat16*)wihhi, (__nv_bfloat16*)wihlo, 0);
    conv_weight<<<(KP * KP + 255) / 256, 256>>>(Whh, (__nv_bfloat16*)whhhi, (__nv_bfloat16*)whhlo, 0);
    tr_lw2<<<(DD * DD + 255) / 256, 256>>>(lw2);
    bmt_kernel<<<KP, 256>>>(Wih);
    bias_kernel<<<1, 256>>>(b2, Wih, bih, bhh);
    padzero_kernel<<<(NN + 255) / 256, 256>>>((__nv_bfloat16*)h1hi, (__nv_bfloat16*)h1lo);

    const int ncv = (NN * 52 + 255) / 256;
    conv_node<<<ncv, 256>>>(node_feat, (__nv_bfloat16*)xhi, (__nv_bfloat16*)xlo, 0);
    conv_node<<<ncv, 256>>>(dyn, (__nv_bfloat16*)h0hi, (__nv_bfloat16*)h0lo, 0);

    // layer 1
    edge_kernel<<<(EE * 50 + 255) / 256, 256>>>(node_feat, src, dst, et, w1);
    mma_gemm<1, true, true><<<NTILES, 256, SM_TOT>>>(
        (const __nv_bfloat16*)xhi, (const __nv_bfloat16*)xlo,
        (const __nv_bfloat16*)w1hi, (const __nv_bfloat16*)w1lo,
        nullptr, nullptr, nullptr, nullptr,
        nullptr, nullptr, nullptr, nullptr,
        b1, (float*)h1_p, (__nv_bfloat16*)h1hi, (__nv_bfloat16*)h1lo);

    // layer 2 scatter + convert
    cudaMemsetAsync(agg_p, 0, sizeof(float) * NN * DD);
    edge_kernel<<<(EE * 50 + 255) / 256, 256>>>((const float*)h1_p, src, dst, et, w2);
    conv_node<<<ncv, 256>>>((const float*)agg_p, (__nv_bfloat16*)a2hi, (__nv_bfloat16*)a2lo, 1);

    // fused final: out = tanh( agg2n@Wih^T + h1@(lw2@Wih^T) + h0@Whh^T + bfin )
    mma_gemm<3, false, false><<<NTILES, 256, SM_TOT>>>(
        (const __nv_bfloat16*)a2hi, (const __nv_bfloat16*)a2lo,
        (const __nv_bfloat16*)wihhi, (const __nv_bfloat16*)wihlo,
        (const __nv_bfloat16*)h1hi, (const __nv_bfloat16*)h1lo,
        (const __nv_bfloat16*)mthi, (const __nv_bfloat16*)mtlo,
        (const __nv_bfloat16*)h0hi, (const __nv_bfloat16*)h0lo,
        (const __nv_bfloat16*)whhhi, (const __nv_bfloat16*)whhlo,
        (const float*)bfin_p, out, nullptr, nullptr);
}

// round 13
// speedup vs baseline: 1.6591x; 1.0317x over previous
#include <cuda_runtime.h>
#include <cuda_bf16.h>
#include <math.h>
#include <stdint.h>

#define NN 50000
#define EE 800000
#define DD 200
#define KP 208            // padded K / padded N for weights
#define BM 128            // M tile per CTA
#define NTILES ((NN + BM - 1) / BM)   // 391

// smem stage layout for GEMM (bytes)
#define SO_AHI 0
#define SO_ALO 18432
#define SO_BHI 36864
#define SO_BLO 66816
#define STAGE_BYTES 96768
#define SM_TOT (2 * STAGE_BYTES)      // 193536

// ================= device scratch =================
__device__ __align__(128) float g_agg[NN * DD];
__device__ __align__(128) float g_h1[NN * DD];
__device__ __align__(128) float g_norm[NN];
__device__ __align__(128) float g_lw2t[DD * DD];
__device__ __align__(128) float g_bfin[DD];
__device__ __align__(128) unsigned long long g_epk[EE];  // (et<<32)|(dst<<16)|src
__device__ __align__(128) __nv_bfloat16 g_xhi[NN * KP],  g_xlo[NN * KP];
__device__ __align__(128) __nv_bfloat16 g_h1hi[NN * KP], g_h1lo[NN * KP];
__device__ __align__(128) __nv_bfloat16 g_a2hi[NN * KP], g_a2lo[NN * KP];
__device__ __align__(128) __nv_bfloat16 g_h0hi[NN * KP], g_h0lo[NN * KP];
__device__ __align__(128) __nv_bfloat16 g_w1hi[KP * KP],  g_w1lo[KP * KP];
__device__ __align__(128) __nv_bfloat16 g_wihhi[KP * KP], g_wihlo[KP * KP];
__device__ __align__(128) __nv_bfloat16 g_whhhi[KP * KP], g_whhlo[KP * KP];
__device__ __align__(128) __nv_bfloat16 g_mthi[KP * KP],  g_mtlo[KP * KP];

// ================= degree / norm / pack =================
__global__ void deg_kernel(const int* __restrict__ dst) {
    int e = blockIdx.x * blockDim.x + threadIdx.x;
    if (e < EE) atomicAdd(&g_norm[dst[e]], 1.0f);
}
__global__ void norm_kernel() {
    int n = blockIdx.x * blockDim.x + threadIdx.x;
    if (n < NN) {
        float d = g_norm[n];
        g_norm[n] = (d > 0.0f) ? (1.0f / d) : 0.0f;
    }
}
__global__ void pack_kernel(const int* __restrict__ src,
                            const int* __restrict__ dst,
                            const int* __restrict__ et) {
    int e = blockIdx.x * blockDim.x + threadIdx.x;
    if (e >= EE) return;
    g_epk[e] = ((unsigned long long)(unsigned)et[e] << 32) |
               ((unsigned long long)(unsigned)dst[e] << 16) |
               (unsigned long long)(unsigned)src[e];
}

// ================= edge message + scatter (packed indices) =================
__global__ void edge_kernel(const float* __restrict__ x,
                            const float* __restrict__ w) {
    int idx = blockIdx.x * blockDim.x + threadIdx.x;
    if (idx >= EE * 50) return;
    int e  = idx / 50;
    int b2 = idx - e * 50;

    unsigned long long pk = __ldg(&g_epk[e]);
    int s = (int)(pk & 0xffff);
    int d = (int)((pk >> 16) & 0xffff);
    int r = (int)(pk >> 32);

    float4 xv = *(const float4*)(x + (long)s * DD + b2 * 4);
    const float4* wp = (const float4*)(w + (long)r * 400 + b2 * 8);
    float4 wA = wp[0];
    float4 wB = wp[1];

    float o0 = xv.x * wA.x + xv.y * wA.z;
    float o1 = xv.x * wA.y + xv.y * wA.w;
    float o2 = xv.z * wB.x + xv.w * wB.z;
    float o3 = xv.z * wB.y + xv.w * wB.w;

    float* ap = g_agg + (long)d * DD + b2 * 4;
    asm volatile("red.global.add.v4.f32 [%0], {%1, %2, %3, %4};"
                 :: "l"(ap), "f"(o0), "f"(o1), "f"(o2), "f"(o3) : "memory");
}

// ================= hi/lo conversions (vectorized 4x) =================
__global__ void conv_node(const float* __restrict__ src,
                          __nv_bfloat16* __restrict__ hi,
                          __nv_bfloat16* __restrict__ lo, int useNorm) {
    int idx = blockIdx.x * blockDim.x + threadIdx.x;   // NN*52
    if (idx >= NN * 52) return;
    int n = idx / 52;
    int c4 = idx - n * 52;
    float4 v = make_float4(0.f, 0.f, 0.f, 0.f);
    if (c4 < 50) {
        v = *(const float4*)(src + (long)n * DD + c4 * 4);
        if (useNorm) {
            float nv = g_norm[n];
            v.x *= nv; v.y *= nv; v.z *= nv; v.w *= nv;
        }
    }
    __nv_bfloat16 h0 = __float2bfloat16(v.x);
    __nv_bfloat16 h1 = __float2bfloat16(v.y);
    __nv_bfloat16 h2 = __float2bfloat16(v.z);
    __nv_bfloat16 h3 = __float2bfloat16(v.w);
    __nv_bfloat162 hp0; hp0.x = h0; hp0.y = h1;
    __nv_bfloat162 hp1; hp1.x = h2; hp1.y = h3;
    __nv_bfloat162 lp0;
    lp0.x = __float2bfloat16(v.x - __bfloat162float(h0));
    lp0.y = __float2bfloat16(v.y - __bfloat162float(h1));
    __nv_bfloat162 lp1;
    lp1.x = __float2bfloat16(v.z - __bfloat162float(h2));
    lp1.y = __float2bfloat16(v.w - __bfloat162float(h3));
    long o = (long)n * KP + c4 * 4;
    *(__nv_bfloat162*)(hi + o) = hp0;
    *(__nv_bfloat162*)(hi + o + 2) = hp1;
    *(__nv_bfloat162*)(lo + o) = lp0;
    *(__nv_bfloat162*)(lo + o + 2) = lp1;
}

// zero only pad columns 200..207 of h1hi/h1lo
__global__ void padzero_kernel(__nv_bfloat16* __restrict__ hi,
                               __nv_bfloat16* __restrict__ lo) {
    int idx = blockIdx.x * blockDim.x + threadIdx.x;   // NN
    if (idx >= NN) return;
    uint4 z = make_uint4(0, 0, 0, 0);
    *(uint4*)(hi + (long)idx * KP + DD) = z;
    *(uint4*)(lo + (long)idx * KP + DD) = z;
}

__global__ void conv_weight(const float* __restrict__ src,
                            __nv_bfloat16* __restrict__ hi,
                            __nv_bfloat16* __restrict__ lo, int transpose) {
    int idx = blockIdx.x * blockDim.x + threadIdx.x;
    if (idx >= KP * KP) return;
    int j = idx / KP;
    int c = idx - j * KP;
    float v = 0.0f;
    if (j < DD && c < DD) v = transpose ? src[c * DD + j] : src[j * DD + c];
    __nv_bfloat16 h = __float2bfloat16(v);
    hi[idx] = h;
    lo[idx] = __float2bfloat16(v - __bfloat162float(h));
}

__global__ void tr_lw2(const float* __restrict__ lw2) {
    int idx = blockIdx.x * blockDim.x + threadIdx.x;
    if (idx >= DD * DD) return;
    int t = idx / DD, u = idx - t * DD;
    g_lw2t[u * DD + t] = lw2[idx];
}

__global__ void bmt_kernel(const float* __restrict__ Wih) {
    __shared__ float row[DD];
    int j = blockIdx.x;
    if (j < DD)
        for (int i = threadIdx.x; i < DD; i += 256) row[i] = Wih[j * DD + i];
    __syncthreads();
    int t = threadIdx.x;
    if (t >= KP) return;
    float s = 0.0f;
    if (j < DD && t < DD) {
#pragma unroll 4
        for (int u = 0; u < DD; u++) s += row[u] * g_lw2t[u * DD + t];
    }
    __nv_bfloat16 h = __float2bfloat16(s);
    g_mthi[j * KP + t] = h;
    g_mtlo[j * KP + t] = __float2bfloat16(s - __bfloat162float(h));
}

__global__ void bias_kernel(const float* __restrict__ b2, const float* __restrict__ Wih,
                            const float* __restrict__ bih, const float* __restrict__ bhh) {
    __shared__ float b2s[DD];
    for (int i = threadIdx.x; i < DD; i += 256) b2s[i] = b2[i];
    __syncthreads();
    int j = threadIdx.x;
    if (j >= DD) return;
    float s = bih[j] + bhh[j];
#pragma unroll 4
    for (int t = 0; t < DD; t++) s += b2s[t] * Wih[j * DD + t];
    g_bfin[j] = s;
}

// ================= mma helpers =================
__device__ __forceinline__ uint32_t smem_u32(const void* p) {
    return (uint32_t)__cvta_generic_to_shared(p);
}
__device__ __forceinline__ void ldsm4(uint32_t* r, uint32_t addr) {
    asm volatile("ldmatrix.sync.aligned.m8n8.x4.shared.b16 {%0,%1,%2,%3}, [%4];"
                 : "=r"(r[0]), "=r"(r[1]), "=r"(r[2]), "=r"(r[3]) : "r"(addr));
}
__device__ __forceinline__ void ldsm2(uint32_t* r, uint32_t addr) {
    asm volatile("ldmatrix.sync.aligned.m8n8.x2.shared.b16 {%0,%1}, [%2];"
                 : "=r"(r[0]), "=r"(r[1]) : "r"(addr));
}
__device__ __forceinline__ void mma_bf16(float* c, const uint32_t* a, const uint32_t* b) {
    asm volatile(
        "mma.sync.aligned.m16n8k16.row.col.f32.bf16.bf16.f32 "
        "{%0,%1,%2,%3}, {%4,%5,%6,%7}, {%8,%9}, {%0,%1,%2,%3};"
        : "+f"(c[0]), "+f"(c[1]), "+f"(c[2]), "+f"(c[3])
        : "r"(a[0]), "r"(a[1]), "r"(a[2]), "r"(a[3]), "r"(b[0]), "r"(b[1]));
}
__device__ __forceinline__ void cpa16(uint32_t dsts, const void* src, bool valid) {
    int sz = valid ? 16 : 0;
    asm volatile("cp.async.cg.shared.global [%0], [%1], 16, %2;"
                 :: "r"(dsts), "l"(src), "r"(sz));
}
#define CP_COMMIT() asm volatile("cp.async.commit_group;" ::: "memory")
#define CP_WAIT1()  asm volatile("cp.async.wait_group 1;" ::: "memory")
#define CP_WAIT0()  asm volatile("cp.async.wait_group 0;" ::: "memory")

// ================= pipelined 3-term MMA GEMM (R6/R10-proven, unchanged) =================
template <int NPASS, bool HAS_AGG, bool WRITE_H1>
__global__ void __launch_bounds__(256, 1) mma_gemm(
    const __nv_bfloat16* __restrict__ A0h, const __nv_bfloat16* __restrict__ A0l,
    const __nv_bfloat16* __restrict__ B0h, const __nv_bfloat16* __restrict__ B0l,
    const __nv_bfloat16* __restrict__ A1h, const __nv_bfloat16* __restrict__ A1l,
    const __nv_bfloat16* __restrict__ B1h, const __nv_bfloat16* __restrict__ B1l,
    const __nv_bfloat16* __restrict__ A2h, const __nv_bfloat16* __restrict__ A2l,
    const __nv_bfloat16* __restrict__ B2h, const __nv_bfloat16* __restrict__ B2l,
    const float* __restrict__ bias, float* __restrict__ outf,
    __nv_bfloat16* __restrict__ h1hi, __nv_bfloat16* __restrict__ h1lo) {
    extern __shared__ __align__(128) char smem[];
    uint32_t sb = smem_u32(smem);

    int tid = threadIdx.x;
    int lane = tid & 31;
    int wid = tid >> 5;
    int wm = wid & 3;
    int wn = wid >> 2;
    int row0 = blockIdx.x * BM;

    float acc[2][13][4];
#pragma unroll
    for (int mi = 0; mi < 2; mi++)
#pragma unroll
        for (int nt = 0; nt < 13; nt++)
#pragma unroll
            for (int q = 0; q < 4; q++) acc[mi][nt][q] = 0.0f;

    const __nv_bfloat16* Ahp[3] = {A0h, A1h, A2h};
    const __nv_bfloat16* Alp[3] = {A0l, A1l, A2l};
    const __nv_bfloat16* Bhp[3] = {B0h, B1h, B2h};
    const __nv_bfloat16* Blp[3] = {B0l, B1l, B2l};

    const int total = NPASS * 4;

    auto load_chunk = [&](int t, int stage) {
        int p = t >> 2, c = t & 3;
        int kb = c * 64;
        int sh = (c == 3) ? 1 : 3;
        int msk = (1 << sh) - 1;
        uint32_t base = sb + stage * STAGE_BYTES;
        const __nv_bfloat16* Ah = Ahp[p];
        const __nv_bfloat16* Al = Alp[p];
        const __nv_bfloat16* Bh = Bhp[p];
        const __nv_bfloat16* Bl = Blp[p];
        int nA = 128 << sh;
        for (int i = tid; i < nA; i += 256) {
            int r = i >> sh, u = i & msk;
            int gr = row0 + r;
            bool v = gr < NN;
            long off = (long)gr * KP + kb + u * 8;
            cpa16(base + SO_AHI + r * 144 + u * 16, Ah + off, v);
            cpa16(base + SO_ALO + r * 144 + u * 16, Al + off, v);
        }
        int nB = 208 << sh;
        for (int i = tid; i < nB; i += 256) {
            int r = i >> sh, u = i & msk;
            long off = (long)r * KP + kb + u * 8;
            cpa16(base + SO_BHI + r * 144 + u * 16, Bh + off, true);
            cpa16(base + SO_BLO + r * 144 + u * 16, Bl + off, true);
        }
        CP_COMMIT();
    };

    uint32_t a_off = (uint32_t)((wm * 32 + (lane & 15)) * 144 + (((lane >> 4) << 3) << 1));
    uint32_t b_off = (uint32_t)((wn * 104 + (lane & 7) + ((lane >> 4) << 3)) * 144 +
                                ((((lane >> 3) & 1) << 3) << 1));
    uint32_t b2_off = (uint32_t)((wn * 104 + 96 + (lane & 7)) * 144 +
                                 ((((lane >> 3) & 1) << 3) << 1));

    load_chunk(0, 0);

#pragma unroll 1
    for (int t = 0; t < total; t++) {
        if (t + 1 < total) {
            load_chunk(t + 1, (t + 1) & 1);
            CP_WAIT1();
        } else {
            CP_WAIT0();
        }
        __syncthreads();

        int c = t & 3;
        int nk16 = (c == 3) ? 1 : 4;
        uint32_t base = sb + (t & 1) * STAGE_BYTES;
#pragma unroll
        for (int k16 = 0; k16 < 4; k16++) {
            if (k16 >= nk16) break;
            uint32_t kofs = (uint32_t)(k16 << 5);
            uint32_t ah[2][4], al[2][4];
#pragma unroll
            for (int mi = 0; mi < 2; mi++) {
                ldsm4(ah[mi], base + SO_AHI + a_off + mi * (16 * 144) + kofs);
                ldsm4(al[mi], base + SO_ALO + a_off + mi * (16 * 144) + kofs);
            }
#pragma unroll
            for (int bt = 0; bt < 6; bt++) {
                uint32_t bh[4], bl[4];
                ldsm4(bh, base + SO_BHI + b_off + bt * (16 * 144) + kofs);
                ldsm4(bl, base + SO_BLO + b_off + bt * (16 * 144) + kofs);
#pragma unroll
                for (int mi = 0; mi < 2; mi++) {
                    mma_bf16(acc[mi][2 * bt],     ah[mi], bh);
                    mma_bf16(acc[mi][2 * bt + 1], ah[mi], bh + 2);
                    mma_bf16(acc[mi][2 * bt],     ah[mi], bl);
                    mma_bf16(acc[mi][2 * bt + 1], ah[mi], bl + 2);
                    mma_bf16(acc[mi][2 * bt],     al[mi], bh);
                    mma_bf16(acc[mi][2 * bt + 1], al[mi], bh + 2);
                }
            }
            {
                uint32_t bh[2], bl[2];
                ldsm2(bh, base + SO_BHI + b2_off + kofs);
                ldsm2(bl, base + SO_BLO + b2_off + kofs);
#pragma unroll
                for (int mi = 0; mi < 2; mi++) {
                    mma_bf16(acc[mi][12], ah[mi], bh);
                    mma_bf16(acc[mi][12], ah[mi], bl);
                    mma_bf16(acc[mi][12], al[mi], bh);
                }
            }
        }
        __syncthreads();
    }

    // ---- epilogue ----
#pragma unroll
    for (int mi = 0; mi < 2; mi++) {
        int r0 = row0 + wm * 32 + mi * 16 + (lane >> 2);
#pragma unroll
        for (int half = 0; half < 2; half++) {
            int gr = r0 + half * 8;
            if (gr >= NN) continue;
            float nv = HAS_AGG ? g_norm[gr] : 0.0f;
#pragma unroll
            for (int nt = 0; nt < 13; nt++) {
                int col = wn * 104 + nt * 8 + ((lane & 3) << 1);
                if (col >= DD) continue;
                float v0 = acc[mi][nt][half * 2 + 0];
                float v1 = acc[mi][nt][half * 2 + 1];
                if (HAS_AGG) {
                    float2 ag = *(const float2*)(g_agg + (long)gr * DD + col);
                    v0 += ag.x * nv;
                    v1 += ag.y * nv;
                }
                float2 bb = *(const float2*)(bias + col);
                v0 = tanhf(v0 + bb.x);
                v1 = tanhf(v1 + bb.y);
                *(float2*)(outf + (long)gr * DD + col) = make_float2(v0, v1);
                if (WRITE_H1) {
                    __nv_bfloat16 h0b = __float2bfloat16(v0);
                    __nv_bfloat16 h1b = __float2bfloat16(v1);
                    __nv_bfloat162 hp; hp.x = h0b; hp.y = h1b;
                    __nv_bfloat162 lp;
                    lp.x = __float2bfloat16(v0 - __bfloat162float(h0b));
                    lp.y = __float2bfloat16(v1 - __bfloat162float(h1b));
                    *(__nv_bfloat162*)(h1hi + (long)gr * KP + col) = hp;
                    *(__nv_bfloat162*)(h1lo + (long)gr * KP + col) = lp;
                }
            }
        }
    }
}

// ================= launch =================
extern "C" void kernel_launch(void* const* d_in, const int* in_sizes, int n_in,
                              void* d_out, int out_size) {
    const float* node_feat = (const float*)d_in[0];
    const float* dyn       = (const float*)d_in[1];
    const int*   src       = (const int*)d_in[2];
    const int*   dst       = (const int*)d_in[3];
    const int*   et        = (const int*)d_in[4];
    const float* w1        = (const float*)d_in[5];
    const float* lw1       = (const float*)d_in[6];
    const float* b1        = (const float*)d_in[7];
    const float* w2        = (const float*)d_in[8];
    const float* lw2       = (const float*)d_in[9];
    const float* b2        = (const float*)d_in[10];
    const float* Wih       = (const float*)d_in[11];
    const float* Whh       = (const float*)d_in[12];
    const float* bih       = (const float*)d_in[13];
    const float* bhh       = (const float*)d_in[14];
    float* out = (float*)d_out;

    void *agg_p, *norm_p, *h1_p, *bfin_p;
    void *xhi, *xlo, *h1hi, *h1lo, *a2hi, *a2lo, *h0hi, *h0lo;
    void *w1hi, *w1lo, *wihhi, *wihlo, *whhhi, *whhlo, *mthi, *mtlo;
    cudaGetSymbolAddress(&agg_p, g_agg);
    cudaGetSymbolAddress(&norm_p, g_norm);
    cudaGetSymbolAddress(&h1_p, g_h1);
    cudaGetSymbolAddress(&bfin_p, g_bfin);
    cudaGetSymbolAddress(&xhi, g_xhi);     cudaGetSymbolAddress(&xlo, g_xlo);
    cudaGetSymbolAddress(&h1hi, g_h1hi);   cudaGetSymbolAddress(&h1lo, g_h1lo);
    cudaGetSymbolAddress(&a2hi, g_a2hi);   cudaGetSymbolAddress(&a2lo, g_a2lo);
    cudaGetSymbolAddress(&h0hi, g_h0hi);   cudaGetSymbolAddress(&h0lo, g_h0lo);
    cudaGetSymbolAddress(&w1hi, g_w1hi);   cudaGetSymbolAddress(&w1lo, g_w1lo);
    cudaGetSymbolAddress(&wihhi, g_wihhi); cudaGetSymbolAddress(&wihlo, g_wihlo);
    cudaGetSymbolAddress(&whhhi, g_whhhi); cudaGetSymbolAddress(&whhlo, g_whhlo);
    cudaGetSymbolAddress(&mthi, g_mthi);   cudaGetSymbolAddress(&mtlo, g_mtlo);

    cudaFuncSetAttribute(mma_gemm<1, true, true>,
                         cudaFuncAttributeMaxDynamicSharedMemorySize, SM_TOT);
    cudaFuncSetAttribute(mma_gemm<3, false, false>,
                         cudaFuncAttributeMaxDynamicSharedMemorySize, SM_TOT);

    cudaMemsetAsync(agg_p, 0, sizeof(float) * NN * DD);
    cudaMemsetAsync(norm_p, 0, sizeof(float) * NN);

    deg_kernel<<<(EE + 255) / 256, 256>>>(dst);
    norm_kernel<<<(NN + 255) / 256, 256>>>();
    pack_kernel<<<(EE + 255) / 256, 256>>>(src, dst, et);

    conv_weight<<<(KP * KP + 255) / 256, 256>>>(lw1, (__nv_bfloat16*)w1hi, (__nv_bfloat16*)w1lo, 1);
    conv_weight<<<(KP * KP + 255) / 256, 256>>>(Wih, (__nv_bfloat16*)wihhi, (__nv_bfloat16*)wihlo, 0);
    conv_weight<<<(KP * KP + 255) / 256, 256>>>(Whh, (__nv_bfloat16*)whhhi, (__nv_bfloat16*)whhlo, 0);
    tr_lw2<<<(DD * DD + 255) / 256, 256>>>(lw2);
    bmt_kernel<<<KP, 256>>>(Wih);
    bias_kernel<<<1, 256>>>(b2, Wih, bih, bhh);
    padzero_kernel<<<(NN + 255) / 256, 256>>>((__nv_bfloat16*)h1hi, (__nv_bfloat16*)h1lo);

    const int ncv = (NN * 52 + 255) / 256;
    conv_node<<<ncv, 256>>>(node_feat, (__nv_bfloat16*)xhi, (__nv_bfloat16*)xlo, 0);
    conv_node<<<ncv, 256>>>(dyn, (__nv_bfloat16*)h0hi, (__nv_bfloat16*)h0lo, 0);

    // layer 1
    edge_kernel<<<(EE * 50 + 255) / 256, 256>>>(node_feat, w1);
    mma_gemm<1, true, true><<<NTILES, 256, SM_TOT>>>(
        (const __nv_bfloat16*)xhi, (const __nv_bfloat16*)xlo,
        (const __nv_bfloat16*)w1hi, (const __nv_bfloat16*)w1lo,
        nullptr, nullptr, nullptr, nullptr,
        nullptr, nullptr, nullptr, nullptr,
        b1, (float*)h1_p, (__nv_bfloat16*)h1hi, (__nv_bfloat16*)h1lo);

    // layer 2 scatter + convert
    cudaMemsetAsync(agg_p, 0, sizeof(float) * NN * DD);
    edge_kernel<<<(EE * 50 + 255) / 256, 256>>>((const float*)h1_p, w2);
    conv_node<<<ncv, 256>>>((const float*)agg_p, (__nv_bfloat16*)a2hi, (__nv_bfloat16*)a2lo, 1);

    // fused final: out = tanh( agg2n@Wih^T + h1@(lw2@Wih^T) + h0@Whh^T + bfin )
    mma_gemm<3, false, false><<<NTILES, 256, SM_TOT>>>(
        (const __nv_bfloat16*)a2hi, (const __nv_bfloat16*)a2lo,
        (const __nv_bfloat16*)wihhi, (const __nv_bfloat16*)wihlo,
        (const __nv_bfloat16*)h1hi, (const __nv_bfloat16*)h1lo,
        (const __nv_bfloat16*)mthi, (const __nv_bfloat16*)mtlo,
        (const __nv_bfloat16*)h0hi, (const __nv_bfloat16*)h0lo,
        (const __nv_bfloat16*)whhhi, (const __nv_bfloat16*)whhlo,
        (const float*)bfin_p, out, nullptr, nullptr);
}

// round 14
// speedup vs baseline: 1.6598x; 1.0004x over previous
#include <cuda_runtime.h>
#include <cuda_bf16.h>
#include <math.h>
#include <stdint.h>

#define NN 50000
#define EE 800000
#define DD 200
#define KP 208            // padded K / padded N for weights
#define BM 64             // M tile per CTA (occupancy-2 retile)
#define NTILES ((NN + BM - 1) / BM)   // 782

// smem stage layout (bytes); K-chunk = 32 cols, row stride 80B
#define SO_AHI 0
#define SO_ALO 5120
#define SO_BHI 10240
#define SO_BLO 26880
#define STAGE_BYTES 43520
#define SM_TOT (2 * STAGE_BYTES)      // 87040 per CTA; 2 CTAs/SM = 174080

// ================= device scratch =================
__device__ __align__(128) float g_agg[NN * DD];
__device__ __align__(128) float g_h1[NN * DD];
__device__ __align__(128) float g_norm[NN];
__device__ __align__(128) float g_lw2t[DD * DD];
__device__ __align__(128) float g_bfin[DD];
__device__ __align__(128) unsigned long long g_epk[EE];  // (et<<32)|(dst<<16)|src
__device__ __align__(128) __nv_bfloat16 g_xhi[NN * KP],  g_xlo[NN * KP];
__device__ __align__(128) __nv_bfloat16 g_h1hi[NN * KP], g_h1lo[NN * KP];
__device__ __align__(128) __nv_bfloat16 g_a2hi[NN * KP], g_a2lo[NN * KP];
__device__ __align__(128) __nv_bfloat16 g_h0hi[NN * KP], g_h0lo[NN * KP];
__device__ __align__(128) __nv_bfloat16 g_w1hi[KP * KP],  g_w1lo[KP * KP];
__device__ __align__(128) __nv_bfloat16 g_wihhi[KP * KP], g_wihlo[KP * KP];
__device__ __align__(128) __nv_bfloat16 g_whhhi[KP * KP], g_whhlo[KP * KP];
__device__ __align__(128) __nv_bfloat16 g_mthi[KP * KP],  g_mtlo[KP * KP];

// ================= degree / norm / pack =================
__global__ void deg_kernel(const int* __restrict__ dst) {
    int e = blockIdx.x * blockDim.x + threadIdx.x;
    if (e < EE) atomicAdd(&g_norm[dst[e]], 1.0f);
}
__global__ void norm_kernel() {
    int n = blockIdx.x * blockDim.x + threadIdx.x;
    if (n < NN) {
        float d = g_norm[n];
        g_norm[n] = (d > 0.0f) ? (1.0f / d) : 0.0f;
    }
}
__global__ void pack_kernel(const int* __restrict__ src,
                            const int* __restrict__ dst,
                            const int* __restrict__ et) {
    int e = blockIdx.x * blockDim.x + threadIdx.x;
    if (e >= EE) return;
    g_epk[e] = ((unsigned long long)(unsigned)et[e] << 32) |
               ((unsigned long long)(unsigned)dst[e] << 16) |
               (unsigned long long)(unsigned)src[e];
}

// ================= edge message + scatter (packed indices) =================
__global__ void edge_kernel(const float* __restrict__ x,
                            const float* __restrict__ w) {
    int idx = blockIdx.x * blockDim.x + threadIdx.x;
    if (idx >= EE * 50) return;
    int e  = idx / 50;
    int b2 = idx - e * 50;

    unsigned long long pk = __ldg(&g_epk[e]);
    int s = (int)(pk & 0xffff);
    int d = (int)((pk >> 16) & 0xffff);
    int r = (int)(pk >> 32);

    float4 xv = *(const float4*)(x + (long)s * DD + b2 * 4);
    const float4* wp = (const float4*)(w + (long)r * 400 + b2 * 8);
    float4 wA = wp[0];
    float4 wB = wp[1];

    float o0 = xv.x * wA.x + xv.y * wA.z;
    float o1 = xv.x * wA.y + xv.y * wA.w;
    float o2 = xv.z * wB.x + xv.w * wB.z;
    float o3 = xv.z * wB.y + xv.w * wB.w;

    float* ap = g_agg + (long)d * DD + b2 * 4;
    asm volatile("red.global.add.v4.f32 [%0], {%1, %2, %3, %4};"
                 :: "l"(ap), "f"(o0), "f"(o1), "f"(o2), "f"(o3) : "memory");
}

// ================= hi/lo conversions (vectorized 4x) =================
__global__ void conv_node(const float* __restrict__ src,
                          __nv_bfloat16* __restrict__ hi,
                          __nv_bfloat16* __restrict__ lo, int useNorm) {
    int idx = blockIdx.x * blockDim.x + threadIdx.x;   // NN*52
    if (idx >= NN * 52) return;
    int n = idx / 52;
    int c4 = idx - n * 52;
    float4 v = make_float4(0.f, 0.f, 0.f, 0.f);
    if (c4 < 50) {
        v = *(const float4*)(src + (long)n * DD + c4 * 4);
        if (useNorm) {
            float nv = g_norm[n];
            v.x *= nv; v.y *= nv; v.z *= nv; v.w *= nv;
        }
    }
    __nv_bfloat16 h0 = __float2bfloat16(v.x);
    __nv_bfloat16 h1 = __float2bfloat16(v.y);
    __nv_bfloat16 h2 = __float2bfloat16(v.z);
    __nv_bfloat16 h3 = __float2bfloat16(v.w);
    __nv_bfloat162 hp0; hp0.x = h0; hp0.y = h1;
    __nv_bfloat162 hp1; hp1.x = h2; hp1.y = h3;
    __nv_bfloat162 lp0;
    lp0.x = __float2bfloat16(v.x - __bfloat162float(h0));
    lp0.y = __float2bfloat16(v.y - __bfloat162float(h1));
    __nv_bfloat162 lp1;
    lp1.x = __float2bfloat16(v.z - __bfloat162float(h2));
    lp1.y = __float2bfloat16(v.w - __bfloat162float(h3));
    long o = (long)n * KP + c4 * 4;
    *(__nv_bfloat162*)(hi + o) = hp0;
    *(__nv_bfloat162*)(hi + o + 2) = hp1;
    *(__nv_bfloat162*)(lo + o) = lp0;
    *(__nv_bfloat162*)(lo + o + 2) = lp1;
}

// zero only pad columns 200..207 of h1hi/h1lo
__global__ void padzero_kernel(__nv_bfloat16* __restrict__ hi,
                               __nv_bfloat16* __restrict__ lo) {
    int idx = blockIdx.x * blockDim.x + threadIdx.x;   // NN
    if (idx >= NN) return;
    uint4 z = make_uint4(0, 0, 0, 0);
    *(uint4*)(hi + (long)idx * KP + DD) = z;
    *(uint4*)(lo + (long)idx * KP + DD) = z;
}

__global__ void conv_weight(const float* __restrict__ src,
                            __nv_bfloat16* __restrict__ hi,
                            __nv_bfloat16* __restrict__ lo, int transpose) {
    int idx = blockIdx.x * blockDim.x + threadIdx.x;
    if (idx >= KP * KP) return;
    int j = idx / KP;
    int c = idx - j * KP;
    float v = 0.0f;
    if (j < DD && c < DD) v = transpose ? src[c * DD + j] : src[j * DD + c];
    __nv_bfloat16 h = __float2bfloat16(v);
    hi[idx] = h;
    lo[idx] = __float2bfloat16(v - __bfloat162float(h));
}

__global__ void tr_lw2(const float* __restrict__ lw2) {
    int idx = blockIdx.x * blockDim.x + threadIdx.x;
    if (idx >= DD * DD) return;
    int t = idx / DD, u = idx - t * DD;
    g_lw2t[u * DD + t] = lw2[idx];
}

__global__ void bmt_kernel(const float* __restrict__ Wih) {
    __shared__ float row[DD];
    int j = blockIdx.x;
    if (j < DD)
        for (int i = threadIdx.x; i < DD; i += 256) row[i] = Wih[j * DD + i];
    __syncthreads();
    int t = threadIdx.x;
    if (t >= KP) return;
    float s = 0.0f;
    if (j < DD && t < DD) {
#pragma unroll 4
        for (int u = 0; u < DD; u++) s += row[u] * g_lw2t[u * DD + t];
    }
    __nv_bfloat16 h = __float2bfloat16(s);
    g_mthi[j * KP + t] = h;
    g_mtlo[j * KP + t] = __float2bfloat16(s - __bfloat162float(h));
}

__global__ void bias_kernel(const float* __restrict__ b2, const float* __restrict__ Wih,
                            const float* __restrict__ bih, const float* __restrict__ bhh) {
    __shared__ float b2s[DD];
    for (int i = threadIdx.x; i < DD; i += 256) b2s[i] = b2[i];
    __syncthreads();
    int j = threadIdx.x;
    if (j >= DD) return;
    float s = bih[j] + bhh[j];
#pragma unroll 4
    for (int t = 0; t < DD; t++) s += b2s[t] * Wih[j * DD + t];
    g_bfin[j] = s;
}

// ================= mma helpers =================
__device__ __forceinline__ uint32_t smem_u32(const void* p) {
    return (uint32_t)__cvta_generic_to_shared(p);
}
__device__ __forceinline__ void ldsm4(uint32_t* r, uint32_t addr) {
    asm volatile("ldmatrix.sync.aligned.m8n8.x4.shared.b16 {%0,%1,%2,%3}, [%4];"
                 : "=r"(r[0]), "=r"(r[1]), "=r"(r[2]), "=r"(r[3]) : "r"(addr));
}
__device__ __forceinline__ void ldsm2(uint32_t* r, uint32_t addr) {
    asm volatile("ldmatrix.sync.aligned.m8n8.x2.shared.b16 {%0,%1}, [%2];"
                 : "=r"(r[0]), "=r"(r[1]) : "r"(addr));
}
__device__ __forceinline__ void mma_bf16(float* c, const uint32_t* a, const uint32_t* b) {
    asm volatile(
        "mma.sync.aligned.m16n8k16.row.col.f32.bf16.bf16.f32 "
        "{%0,%1,%2,%3}, {%4,%5,%6,%7}, {%8,%9}, {%0,%1,%2,%3};"
        : "+f"(c[0]), "+f"(c[1]), "+f"(c[2]), "+f"(c[3])
        : "r"(a[0]), "r"(a[1]), "r"(a[2]), "r"(a[3]), "r"(b[0]), "r"(b[1]));
}
__device__ __forceinline__ void cpa16(uint32_t dsts, const void* src, bool valid) {
    int sz = valid ? 16 : 0;
    asm volatile("cp.async.cg.shared.global [%0], [%1], 16, %2;"
                 :: "r"(dsts), "l"(src), "r"(sz));
}
#define CP_COMMIT() asm volatile("cp.async.commit_group;" ::: "memory")
#define CP_WAIT1()  asm volatile("cp.async.wait_group 1;" ::: "memory")
#define CP_WAIT0()  asm volatile("cp.async.wait_group 0;" ::: "memory")

// ================= occupancy-2 3-term MMA GEMM (BM=64, K-chunk=32) =================
// C[64 x 200] per CTA: C = sum_p (AhiBhi + AhiBlo + AloBhi)_p
// 8 warps 4(M: 16 rows each) x 2(N: 104 cols). acc = 13x4 = 52 regs.
// 2 CTAs/SM co-resident: each CTA's sync/ldsm bubbles hidden by the other.
template <int NPASS, bool HAS_AGG, bool WRITE_H1>
__global__ void __launch_bounds__(256, 2) mma_gemm(
    const __nv_bfloat16* __restrict__ A0h, const __nv_bfloat16* __restrict__ A0l,
    const __nv_bfloat16* __restrict__ B0h, const __nv_bfloat16* __restrict__ B0l,
    const __nv_bfloat16* __restrict__ A1h, const __nv_bfloat16* __restrict__ A1l,
    const __nv_bfloat16* __restrict__ B1h, const __nv_bfloat16* __restrict__ B1l,
    const __nv_bfloat16* __restrict__ A2h, const __nv_bfloat16* __restrict__ A2l,
    const __nv_bfloat16* __restrict__ B2h, const __nv_bfloat16* __restrict__ B2l,
    const float* __restrict__ bias, float* __restrict__ outf,
    __nv_bfloat16* __restrict__ h1hi, __nv_bfloat16* __restrict__ h1lo) {
    extern __shared__ __align__(128) char smem[];
    uint32_t sb = smem_u32(smem);

    int tid = threadIdx.x;
    int lane = tid & 31;
    int wid = tid >> 5;
    int wm = wid & 3;          // 0..3 -> M offset wm*16
    int wn = wid >> 2;         // 0..1 -> N offset wn*104
    int row0 = blockIdx.x * BM;

    float acc[13][4];
#pragma unroll
    for (int nt = 0; nt < 13; nt++)
#pragma unroll
        for (int q = 0; q < 4; q++) acc[nt][q] = 0.0f;

    const __nv_bfloat16* Ahp[3] = {A0h, A1h, A2h};
    const __nv_bfloat16* Alp[3] = {A0l, A1l, A2l};
    const __nv_bfloat16* Bhp[3] = {B0h, B1h, B2h};
    const __nv_bfloat16* Blp[3] = {B0l, B1l, B2l};

    const int total = NPASS * 7;   // 7 chunks per pass: {32x6, 16}

    // ---- chunk loader (cp.async) ----
    auto load_chunk = [&](int t, int stage) {
        int p = t / 7, c = t - p * 7;
        int kb = c * 32;
        int sh = (c == 6) ? 1 : 2;          // uint4 per row = 1<<sh
        int msk = (1 << sh) - 1;
        uint32_t base = sb + stage * STAGE_BYTES;
        const __nv_bfloat16* Ah = Ahp[p];
        const __nv_bfloat16* Al = Alp[p];
        const __nv_bfloat16* Bh = Bhp[p];
        const __nv_bfloat16* Bl = Blp[p];
        int nA = 64 << sh;
        for (int i = tid; i < nA; i += 256) {
            int r = i >> sh, u = i & msk;
            int gr = row0 + r;
            bool v = gr < NN;
            long off = (long)gr * KP + kb + u * 8;
            cpa16(base + SO_AHI + r * 80 + u * 16, Ah + off, v);
            cpa16(base + SO_ALO + r * 80 + u * 16, Al + off, v);
        }
        int nB = 208 << sh;
        for (int i = tid; i < nB; i += 256) {
            int r = i >> sh, u = i & msk;
            long off = (long)r * KP + kb + u * 8;
            cpa16(base + SO_BHI + r * 80 + u * 16, Bh + off, true);
            cpa16(base + SO_BLO + r * 80 + u * 16, Bl + off, true);
        }
        CP_COMMIT();
    };

    // per-lane fragment byte offsets within a stage (row stride 80B)
    uint32_t a_off = (uint32_t)((wm * 16 + (lane & 15)) * 80 + (((lane >> 4) << 3) << 1));
    uint32_t b_off = (uint32_t)((wn * 104 + (lane & 7) + ((lane >> 4) << 3)) * 80 +
                                ((((lane >> 3) & 1) << 3) << 1));
    uint32_t b2_off = (uint32_t)((wn * 104 + 96 + (lane & 7)) * 80 +
                                 ((((lane >> 3) & 1) << 3) << 1));

    load_chunk(0, 0);

#pragma unroll 1
    for (int t = 0; t < total; t++) {
        if (t + 1 < total) {
            load_chunk(t + 1, (t + 1) & 1);
            CP_WAIT1();
        } else {
            CP_WAIT0();
        }
        __syncthreads();

        int c = t - (t / 7) * 7;
        int nk16 = (c == 6) ? 1 : 2;
        uint32_t base = sb + (t & 1) * STAGE_BYTES;
#pragma unroll
        for (int k16 = 0; k16 < 2; k16++) {
            if (k16 >= nk16) break;
            uint32_t kofs = (uint32_t)(k16 << 5);   // 16 bf16 = 32 bytes
            uint32_t ah[4], al[4];
            ldsm4(ah, base + SO_AHI + a_off + kofs);
            ldsm4(al, base + SO_ALO + a_off + kofs);
#pragma unroll
            for (int bt = 0; bt < 6; bt++) {
                uint32_t bh[4], bl[4];
                ldsm4(bh, base + SO_BHI + b_off + bt * (16 * 80) + kofs);
                ldsm4(bl, base + SO_BLO + b_off + bt * (16 * 80) + kofs);
                mma_bf16(acc[2 * bt],     ah, bh);
                mma_bf16(acc[2 * bt + 1], ah, bh + 2);
                mma_bf16(acc[2 * bt],     ah, bl);
                mma_bf16(acc[2 * bt + 1], ah, bl + 2);
                mma_bf16(acc[2 * bt],     al, bh);
                mma_bf16(acc[2 * bt + 1], al, bh + 2);
            }
            {
                uint32_t bh[2], bl[2];
                ldsm2(bh, base + SO_BHI + b2_off + kofs);
                ldsm2(bl, base + SO_BLO + b2_off + kofs);
                mma_bf16(acc[12], ah, bh);
                mma_bf16(acc[12], ah, bl);
                mma_bf16(acc[12], al, bh);
            }
        }
        __syncthreads();
    }

    // ---- epilogue ----
    int r0 = row0 + wm * 16 + (lane >> 2);
#pragma unroll
    for (int half = 0; half < 2; half++) {
        int gr = r0 + half * 8;
        if (gr >= NN) continue;
        float nv = HAS_AGG ? g_norm[gr] : 0.0f;
#pragma unroll
        for (int nt = 0; nt < 13; nt++) {
            int col = wn * 104 + nt * 8 + ((lane & 3) << 1);
            if (col >= DD) continue;
            float v0 = acc[nt][half * 2 + 0];
            float v1 = acc[nt][half * 2 + 1];
            if (HAS_AGG) {
                float2 ag = *(const float2*)(g_agg + (long)gr * DD + col);
                v0 += ag.x * nv;
                v1 += ag.y * nv;
            }
            float2 bb = *(const float2*)(bias + col);
            v0 = tanhf(v0 + bb.x);
            v1 = tanhf(v1 + bb.y);
            *(float2*)(outf + (long)gr * DD + col) = make_float2(v0, v1);
            if (WRITE_H1) {
                __nv_bfloat16 h0b = __float2bfloat16(v0);
                __nv_bfloat16 h1b = __float2bfloat16(v1);
                __nv_bfloat162 hp; hp.x = h0b; hp.y = h1b;
                __nv_bfloat162 lp;
                lp.x = __float2bfloat16(v0 - __bfloat162float(h0b));
                lp.y = __float2bfloat16(v1 - __bfloat162float(h1b));
                *(__nv_bfloat162*)(h1hi + (long)gr * KP + col) = hp;
                *(__nv_bfloat162*)(h1lo + (long)gr * KP + col) = lp;
            }
        }
    }
}

// ================= launch =================
extern "C" void kernel_launch(void* const* d_in, const int* in_sizes, int n_in,
                              void* d_out, int out_size) {
    const float* node_feat = (const float*)d_in[0];
    const float* dyn       = (const float*)d_in[1];
    const int*   src       = (const int*)d_in[2];
    const int*   dst       = (const int*)d_in[3];
    const int*   et        = (const int*)d_in[4];
    const float* w1        = (const float*)d_in[5];
    const float* lw1       = (const float*)d_in[6];
    const float* b1        = (const float*)d_in[7];
    const float* w2        = (const float*)d_in[8];
    const float* lw2       = (const float*)d_in[9];
    const float* b2        = (const float*)d_in[10];
    const float* Wih       = (const float*)d_in[11];
    const float* Whh       = (const float*)d_in[12];
    const float* bih       = (const float*)d_in[13];
    const float* bhh       = (const float*)d_in[14];
    float* out = (float*)d_out;

    void *agg_p, *norm_p, *h1_p, *bfin_p;
    void *xhi, *xlo, *h1hi, *h1lo, *a2hi, *a2lo, *h0hi, *h0lo;
    void *w1hi, *w1lo, *wihhi, *wihlo, *whhhi, *whhlo, *mthi, *mtlo;
    cudaGetSymbolAddress(&agg_p, g_agg);
    cudaGetSymbolAddress(&norm_p, g_norm);
    cudaGetSymbolAddress(&h1_p, g_h1);
    cudaGetSymbolAddress(&bfin_p, g_bfin);
    cudaGetSymbolAddress(&xhi, g_xhi);     cudaGetSymbolAddress(&xlo, g_xlo);
    cudaGetSymbolAddress(&h1hi, g_h1hi);   cudaGetSymbolAddress(&h1lo, g_h1lo);
    cudaGetSymbolAddress(&a2hi, g_a2hi);   cudaGetSymbolAddress(&a2lo, g_a2lo);
    cudaGetSymbolAddress(&h0hi, g_h0hi);   cudaGetSymbolAddress(&h0lo, g_h0lo);
    cudaGetSymbolAddress(&w1hi, g_w1hi);   cudaGetSymbolAddress(&w1lo, g_w1lo);
    cudaGetSymbolAddress(&wihhi, g_wihhi); cudaGetSymbolAddress(&wihlo, g_wihlo);
    cudaGetSymbolAddress(&whhhi, g_whhhi); cudaGetSymbolAddress(&whhlo, g_whhlo);
    cudaGetSymbolAddress(&mthi, g_mthi);   cudaGetSymbolAddress(&mtlo, g_mtlo);

    cudaFuncSetAttribute(mma_gemm<1, true, true>,
                         cudaFuncAttributeMaxDynamicSharedMemorySize, SM_TOT);
    cudaFuncSetAttribute(mma_gemm<3, false, false>,
                         cudaFuncAttributeMaxDynamicSharedMemorySize, SM_TOT);

    cudaMemsetAsync(agg_p, 0, sizeof(float) * NN * DD);
    cudaMemsetAsync(norm_p, 0, sizeof(float) * NN);

    deg_kernel<<<(EE + 255) / 256, 256>>>(dst);
    norm_kernel<<<(NN + 255) / 256, 256>>>();
    pack_kernel<<<(EE + 255) / 256, 256>>>(src, dst, et);

    conv_weight<<<(KP * KP + 255) / 256, 256>>>(lw1, (__nv_bfloat16*)w1hi, (__nv_bfloat16*)w1lo, 1);
    conv_weight<<<(KP * KP + 255) / 256, 256>>>(Wih, (__nv_bfloat16*)wihhi, (__nv_bfloat16*)wihlo, 0);
    conv_weight<<<(KP * KP + 255) / 256, 256>>>(Whh, (__nv_bfloat16*)whhhi, (__nv_bfloat16*)whhlo, 0);
    tr_lw2<<<(DD * DD + 255) / 256, 256>>>(lw2);
    bmt_kernel<<<KP, 256>>>(Wih);
    bias_kernel<<<1, 256>>>(b2, Wih, bih, bhh);
    padzero_kernel<<<(NN + 255) / 256, 256>>>((__nv_bfloat16*)h1hi, (__nv_bfloat16*)h1lo);

    const int ncv = (NN * 52 + 255) / 256;
    conv_node<<<ncv, 256>>>(node_feat, (__nv_bfloat16*)xhi, (__nv_bfloat16*)xlo, 0);
    conv_node<<<ncv, 256>>>(dyn, (__nv_bfloat16*)h0hi, (__nv_bfloat16*)h0lo, 0);

    // layer 1
    edge_kernel<<<(EE * 50 + 255) / 256, 256>>>(node_feat, w1);
    mma_gemm<1, true, true><<<NTILES, 256, SM_TOT>>>(
        (const __nv_bfloat16*)xhi, (const __nv_bfloat16*)xlo,
        (const __nv_bfloat16*)w1hi, (const __nv_bfloat16*)w1lo,
        nullptr, nullptr, nullptr, nullptr,
        nullptr, nullptr, nullptr, nullptr,
        b1, (float*)h1_p, (__nv_bfloat16*)h1hi, (__nv_bfloat16*)h1lo);

    // layer 2 scatter + convert
    cudaMemsetAsync(agg_p, 0, sizeof(float) * NN * DD);
    edge_kernel<<<(EE * 50 + 255) / 256, 256>>>((const float*)h1_p, w2);
    conv_node<<<ncv, 256>>>((const float*)agg_p, (__nv_bfloat16*)a2hi, (__nv_bfloat16*)a2lo, 1);

    // fused final: out = tanh( agg2n@Wih^T + h1@(lw2@Wih^T) + h0@Whh^T + bfin )
    mma_gemm<3, false, false><<<NTILES, 256, SM_TOT>>>(
        (const __nv_bfloat16*)a2hi, (const __nv_bfloat16*)a2lo,
        (const __nv_bfloat16*)wihhi, (const __nv_bfloat16*)wihlo,
        (const __nv_bfloat16*)h1hi, (const __nv_bfloat16*)h1lo,
        (const __nv_bfloat16*)mthi, (const __nv_bfloat16*)mtlo,
        (const __nv_bfloat16*)h0hi, (const __nv_bfloat16*)h0lo,
        (const __nv_bfloat16*)whhhi, (const __nv_bfloat16*)whhlo,
        (const float*)bfin_p, out, nullptr, nullptr);
}

// round 15
// speedup vs baseline: 1.7749x; 1.0693x over previous
#include <cuda_runtime.h>
#include <cuda_bf16.h>
#include <math.h>
#include <stdint.h>

#define NN 50000
#define EE 800000
#define DD 200
#define KP 208            // padded K / padded N for weights
#define BM 64             // M tile per CTA (occupancy-2 retile, R14-proven)
#define NTILES ((NN + BM - 1) / BM)   // 782

// smem stage layout (bytes); K-chunk = 32 cols, row stride 80B
#define SO_AHI 0
#define SO_ALO 5120
#define SO_BHI 10240
#define SO_BLO 26880
#define STAGE_BYTES 43520
#define SM_TOT (2 * STAGE_BYTES)      // 87040 per CTA; 2 CTAs/SM

// mega_prep role block counts (256 threads/block)
#define CNB   ((NN * 52 + 255) / 256)   // 10157 conv_node
#define CWB   ((KP * KP + 255) / 256)   // 169 conv_weight
#define BMTB  (13 * 13)                 // 169 bmt tiles (16x16 over 208x208)
#define PZB   ((NN + 255) / 256)        // 196 padzero
#define DEGB  ((EE + 255) / 256)        // 3125 deg
#define PKB   ((EE + 255) / 256)        // 3125 pack
#define MEGA_GRID (2 * CNB + 3 * CWB + BMTB + 1 + PZB + DEGB + PKB)

// ================= device scratch =================
__device__ __align__(128) float g_agg[NN * DD];
__device__ __align__(128) float g_h1[NN * DD];
__device__ __align__(128) float g_norm[NN];      // deg counts -> 1/deg
__device__ __align__(128) float g_bfin[DD];
__device__ __align__(128) unsigned long long g_epk[EE];  // (et<<32)|(dst<<16)|src
__device__ __align__(128) __nv_bfloat16 g_xhi[NN * KP],  g_xlo[NN * KP];
__device__ __align__(128) __nv_bfloat16 g_h1hi[NN * KP], g_h1lo[NN * KP];
__device__ __align__(128) __nv_bfloat16 g_a2hi[NN * KP], g_a2lo[NN * KP];
__device__ __align__(128) __nv_bfloat16 g_h0hi[NN * KP], g_h0lo[NN * KP];
__device__ __align__(128) __nv_bfloat16 g_w1hi[KP * KP],  g_w1lo[KP * KP];
__device__ __align__(128) __nv_bfloat16 g_wihhi[KP * KP], g_wihlo[KP * KP];
__device__ __align__(128) __nv_bfloat16 g_whhhi[KP * KP], g_whhlo[KP * KP];
__device__ __align__(128) __nv_bfloat16 g_mthi[KP * KP],  g_mtlo[KP * KP];

// ================= role bodies =================
__device__ __forceinline__ void conv_node_body(int idx, const float* __restrict__ src,
                                               __nv_bfloat16* __restrict__ hi,
                                               __nv_bfloat16* __restrict__ lo,
                                               bool useNorm) {
    if (idx >= NN * 52) return;
    int n = idx / 52;
    int c4 = idx - n * 52;
    float4 v = make_float4(0.f, 0.f, 0.f, 0.f);
    if (c4 < 50) {
        v = *(const float4*)(src + (long)n * DD + c4 * 4);
        if (useNorm) {
            float nv = g_norm[n];
            v.x *= nv; v.y *= nv; v.z *= nv; v.w *= nv;
        }
    }
    __nv_bfloat16 h0 = __float2bfloat16(v.x);
    __nv_bfloat16 h1 = __float2bfloat16(v.y);
    __nv_bfloat16 h2 = __float2bfloat16(v.z);
    __nv_bfloat16 h3 = __float2bfloat16(v.w);
    __nv_bfloat162 hp0; hp0.x = h0; hp0.y = h1;
    __nv_bfloat162 hp1; hp1.x = h2; hp1.y = h3;
    __nv_bfloat162 lp0;
    lp0.x = __float2bfloat16(v.x - __bfloat162float(h0));
    lp0.y = __float2bfloat16(v.y - __bfloat162float(h1));
    __nv_bfloat162 lp1;
    lp1.x = __float2bfloat16(v.z - __bfloat162float(h2));
    lp1.y = __float2bfloat16(v.w - __bfloat162float(h3));
    long o = (long)n * KP + c4 * 4;
    *(__nv_bfloat162*)(hi + o) = hp0;
    *(__nv_bfloat162*)(hi + o + 2) = hp1;
    *(__nv_bfloat162*)(lo + o) = lp0;
    *(__nv_bfloat162*)(lo + o + 2) = lp1;
}

__device__ __forceinline__ void conv_weight_body(int idx, const float* __restrict__ src,
                                                 __nv_bfloat16* __restrict__ hi,
                                                 __nv_bfloat16* __restrict__ lo,
                                                 bool transpose) {
    if (idx >= KP * KP) return;
    int j = idx / KP;
    int c = idx - j * KP;
    float v = 0.0f;
    if (j < DD && c < DD) v = transpose ? src[c * DD + j] : src[j * DD + c];
    __nv_bfloat16 h = __float2bfloat16(v);
    hi[idx] = h;
    lo[idx] = __float2bfloat16(v - __bfloat162float(h));
}

// ================= mega_prep: all independent prep in one launch =================
__global__ __launch_bounds__(256) void mega_prep(
    const float* __restrict__ x, const float* __restrict__ dyn,
    const int* __restrict__ src, const int* __restrict__ dst,
    const int* __restrict__ et,
    const float* __restrict__ lw1, const float* __restrict__ Wih,
    const float* __restrict__ Whh, const float* __restrict__ lw2,
    const float* __restrict__ b2, const float* __restrict__ bih,
    const float* __restrict__ bhh) {
    __shared__ float sh[544];
    int b = blockIdx.x;
    int tid = threadIdx.x;

    if (b < CNB) {                       // conv x -> xhi/xlo
        conv_node_body(b * 256 + tid, x, g_xhi, g_xlo, false);
        return;
    }
    b -= CNB;
    if (b < CNB) {                       // conv h0 -> h0hi/h0lo
        conv_node_body(b * 256 + tid, dyn, g_h0hi, g_h0lo, false);
        return;
    }
    b -= CNB;
    if (b < CWB) {                       // lw1^T -> w1hi/lo
        conv_weight_body(b * 256 + tid, lw1, g_w1hi, g_w1lo, true);
        return;
    }
    b -= CWB;
    if (b < CWB) {                       // Wih -> wihhi/lo
        conv_weight_body(b * 256 + tid, Wih, g_wihhi, g_wihlo, false);
        return;
    }
    b -= CWB;
    if (b < CWB) {                       // Whh -> whhhi/lo
        conv_weight_body(b * 256 + tid, Whh, g_whhhi, g_whhlo, false);
        return;
    }
    b -= CWB;
    if (b < BMTB) {                      // Mt[j][t] = sum_u Wih[j,u]*lw2[t,u] (16x16 tiles)
        int tj = (b / 13) * 16;
        int tt = (b % 13) * 16;
        float* Ws = sh;                  // [16][17]
        float* Ls = sh + 272;            // [16][17]
        int r = tid >> 4, cth = tid & 15;
        float s = 0.0f;
        for (int kb = 0; kb < DD; kb += 16) {
            int gk = kb + cth;
            int gj = tj + r, gt = tt + r;
            Ws[r * 17 + cth] = (gj < DD && gk < DD) ? Wih[gj * DD + gk] : 0.0f;
            Ls[r * 17 + cth] = (gt < DD && gk < DD) ? lw2[gt * DD + gk] : 0.0f;
            __syncthreads();
#pragma unroll
            for (int u = 0; u < 16; u++) s += Ws[r * 17 + u] * Ls[cth * 17 + u];
            __syncthreads();
        }
        int gj = tj + r, gt = tt + cth;
        if (gj < KP && gt < KP) {
            __nv_bfloat16 h = __float2bfloat16(s);
            g_mthi[gj * KP + gt] = h;
            g_mtlo[gj * KP + gt] = __float2bfloat16(s - __bfloat162float(h));
        }
        return;
    }
    b -= BMTB;
    if (b == 0) {                        // bfin[j] = bih + bhh + b2 @ Wih^T
        for (int i = tid; i < DD; i += 256) sh[i] = b2[i];
        __syncthreads();
        if (tid < DD) {
            float s = bih[tid] + bhh[tid];
#pragma unroll 4
            for (int t = 0; t < DD; t++) s += sh[t] * Wih[tid * DD + t];
            g_bfin[tid] = s;
        }
        return;
    }
    b -= 1;
    if (b < PZB) {                       // zero pad cols 200..207 of h1hi/h1lo
        int idx = b * 256 + tid;
        if (idx < NN) {
            uint4 z = make_uint4(0, 0, 0, 0);
            *(uint4*)(g_h1hi + (long)idx * KP + DD) = z;
            *(uint4*)(g_h1lo + (long)idx * KP + DD) = z;
        }
        return;
    }
    b -= PZB;
    if (b < DEGB) {                      // degree histogram
        int e = b * 256 + tid;
        if (e < EE) atomicAdd(&g_norm[dst[e]], 1.0f);
        return;
    }
    b -= DEGB;
    {                                    // pack edge indices
        int e = b * 256 + tid;
        if (e < EE)
            g_epk[e] = ((unsigned long long)(unsigned)et[e] << 32) |
                       ((unsigned long long)(unsigned)dst[e] << 16) |
                       (unsigned long long)(unsigned)src[e];
    }
}

// ================= norm (separate: needs all deg atomics done) =================
__global__ void norm_kernel() {
    int n = blockIdx.x * blockDim.x + threadIdx.x;
    if (n < NN) {
        float d = g_norm[n];
        g_norm[n] = (d > 0.0f) ? (1.0f / d) : 0.0f;
    }
}

// ================= edge message + scatter (packed indices, R13-proven) =================
__global__ void edge_kernel(const float* __restrict__ x,
                            const float* __restrict__ w) {
    int idx = blockIdx.x * blockDim.x + threadIdx.x;
    if (idx >= EE * 50) return;
    int e  = idx / 50;
    int b2 = idx - e * 50;

    unsigned long long pk = __ldg(&g_epk[e]);
    int s = (int)(pk & 0xffff);
    int d = (int)((pk >> 16) & 0xffff);
    int r = (int)(pk >> 32);

    float4 xv = *(const float4*)(x + (long)s * DD + b2 * 4);
    const float4* wp = (const float4*)(w + (long)r * 400 + b2 * 8);
    float4 wA = wp[0];
    float4 wB = wp[1];

    float o0 = xv.x * wA.x + xv.y * wA.z;
    float o1 = xv.x * wA.y + xv.y * wA.w;
    float o2 = xv.z * wB.x + xv.w * wB.z;
    float o3 = xv.z * wB.y + xv.w * wB.w;

    float* ap = g_agg + (long)d * DD + b2 * 4;
    asm volatile("red.global.add.v4.f32 [%0], {%1, %2, %3, %4};"
                 :: "l"(ap), "f"(o0), "f"(o1), "f"(o2), "f"(o3) : "memory");
}

// ================= standalone conv (agg2 -> a2hi/lo, normalized) =================
__global__ void conv_node(const float* __restrict__ src,
                          __nv_bfloat16* __restrict__ hi,
                          __nv_bfloat16* __restrict__ lo, int useNorm) {
    conv_node_body(blockIdx.x * 256 + threadIdx.x, src, hi, lo, useNorm != 0);
}

// ================= mma helpers =================
__device__ __forceinline__ uint32_t smem_u32(const void* p) {
    return (uint32_t)__cvta_generic_to_shared(p);
}
__device__ __forceinline__ void ldsm4(uint32_t* r, uint32_t addr) {
    asm volatile("ldmatrix.sync.aligned.m8n8.x4.shared.b16 {%0,%1,%2,%3}, [%4];"
                 : "=r"(r[0]), "=r"(r[1]), "=r"(r[2]), "=r"(r[3]) : "r"(addr));
}
__device__ __forceinline__ void ldsm2(uint32_t* r, uint32_t addr) {
    asm volatile("ldmatrix.sync.aligned.m8n8.x2.shared.b16 {%0,%1}, [%2];"
                 : "=r"(r[0]), "=r"(r[1]) : "r"(addr));
}
__device__ __forceinline__ void mma_bf16(float* c, const uint32_t* a, const uint32_t* b) {
    asm volatile(
        "mma.sync.aligned.m16n8k16.row.col.f32.bf16.bf16.f32 "
        "{%0,%1,%2,%3}, {%4,%5,%6,%7}, {%8,%9}, {%0,%1,%2,%3};"
        : "+f"(c[0]), "+f"(c[1]), "+f"(c[2]), "+f"(c[3])
        : "r"(a[0]), "r"(a[1]), "r"(a[2]), "r"(a[3]), "r"(b[0]), "r"(b[1]));
}
__device__ __forceinline__ void cpa16(uint32_t dsts, const void* src, bool valid) {
    int sz = valid ? 16 : 0;
    asm volatile("cp.async.cg.shared.global [%0], [%1], 16, %2;"
                 :: "r"(dsts), "l"(src), "r"(sz));
}
#define CP_COMMIT() asm volatile("cp.async.commit_group;" ::: "memory")
#define CP_WAIT1()  asm volatile("cp.async.wait_group 1;" ::: "memory")
#define CP_WAIT0()  asm volatile("cp.async.wait_group 0;" ::: "memory")

// ================= occupancy-2 3-term MMA GEMM (R14-proven, unchanged) =================
template <int NPASS, bool HAS_AGG, bool WRITE_H1>
__global__ void __launch_bounds__(256, 2) mma_gemm(
    const __nv_bfloat16* __restrict__ A0h, const __nv_bfloat16* __restrict__ A0l,
    const __nv_bfloat16* __restrict__ B0h, const __nv_bfloat16* __restrict__ B0l,
    const __nv_bfloat16* __restrict__ A1h, const __nv_bfloat16* __restrict__ A1l,
    const __nv_bfloat16* __restrict__ B1h, const __nv_bfloat16* __restrict__ B1l,
    const __nv_bfloat16* __restrict__ A2h, const __nv_bfloat16* __restrict__ A2l,
    const __nv_bfloat16* __restrict__ B2h, const __nv_bfloat16* __restrict__ B2l,
    const float* __restrict__ bias, float* __restrict__ outf,
    __nv_bfloat16* __restrict__ h1hi, __nv_bfloat16* __restrict__ h1lo) {
    extern __shared__ __align__(128) char smem[];
    uint32_t sb = smem_u32(smem);

    int tid = threadIdx.x;
    int lane = tid & 31;
    int wid = tid >> 5;
    int wm = wid & 3;
    int wn = wid >> 2;
    int row0 = blockIdx.x * BM;

    float acc[13][4];
#pragma unroll
    for (int nt = 0; nt < 13; nt++)
#pragma unroll
        for (int q = 0; q < 4; q++) acc[nt][q] = 0.0f;

    const __nv_bfloat16* Ahp[3] = {A0h, A1h, A2h};
    const __nv_bfloat16* Alp[3] = {A0l, A1l, A2l};
    const __nv_bfloat16* Bhp[3] = {B0h, B1h, B2h};
    const __nv_bfloat16* Blp[3] = {B0l, B1l, B2l};

    const int total = NPASS * 7;

    auto load_chunk = [&](int t, int stage) {
        int p = t / 7, c = t - p * 7;
        int kb = c * 32;
        int sh = (c == 6) ? 1 : 2;
        int msk = (1 << sh) - 1;
        uint32_t base = sb + stage * STAGE_BYTES;
        const __nv_bfloat16* Ah = Ahp[p];
        const __nv_bfloat16* Al = Alp[p];
        const __nv_bfloat16* Bh = Bhp[p];
        const __nv_bfloat16* Bl = Blp[p];
        int nA = 64 << sh;
        for (int i = tid; i < nA; i += 256) {
            int r = i >> sh, u = i & msk;
            int gr = row0 + r;
            bool v = gr < NN;
            long off = (long)gr * KP + kb + u * 8;
            cpa16(base + SO_AHI + r * 80 + u * 16, Ah + off, v);
            cpa16(base + SO_ALO + r * 80 + u * 16, Al + off, v);
        }
        int nB = 208 << sh;
        for (int i = tid; i < nB; i += 256) {
            int r = i >> sh, u = i & msk;
            long off = (long)r * KP + kb + u * 8;
            cpa16(base + SO_BHI + r * 80 + u * 16, Bh + off, true);
            cpa16(base + SO_BLO + r * 80 + u * 16, Bl + off, true);
        }
        CP_COMMIT();
    };

    uint32_t a_off = (uint32_t)((wm * 16 + (lane & 15)) * 80 + (((lane >> 4) << 3) << 1));
    uint32_t b_off = (uint32_t)((wn * 104 + (lane & 7) + ((lane >> 4) << 3)) * 80 +
                                ((((lane >> 3) & 1) << 3) << 1));
    uint32_t b2_off = (uint32_t)((wn * 104 + 96 + (lane & 7)) * 80 +
                                 ((((lane >> 3) & 1) << 3) << 1));

    load_chunk(0, 0);

#pragma unroll 1
    for (int t = 0; t < total; t++) {
        if (t + 1 < total) {
            load_chunk(t + 1, (t + 1) & 1);
            CP_WAIT1();
        } else {
            CP_WAIT0();
        }
        __syncthreads();

        int c = t - (t / 7) * 7;
        int nk16 = (c == 6) ? 1 : 2;
        uint32_t base = sb + (t & 1) * STAGE_BYTES;
#pragma unroll
        for (int k16 = 0; k16 < 2; k16++) {
            if (k16 >= nk16) break;
            uint32_t kofs = (uint32_t)(k16 << 5);
            uint32_t ah[4], al[4];
            ldsm4(ah, base + SO_AHI + a_off + kofs);
            ldsm4(al, base + SO_ALO + a_off + kofs);
#pragma unroll
            for (int bt = 0; bt < 6; bt++) {
                uint32_t bh[4], bl[4];
                ldsm4(bh, base + SO_BHI + b_off + bt * (16 * 80) + kofs);
                ldsm4(bl, base + SO_BLO + b_off + bt * (16 * 80) + kofs);
                mma_bf16(acc[2 * bt],     ah, bh);
                mma_bf16(acc[2 * bt + 1], ah, bh + 2);
                mma_bf16(acc[2 * bt],     ah, bl);
                mma_bf16(acc[2 * bt + 1], ah, bl + 2);
                mma_bf16(acc[2 * bt],     al, bh);
                mma_bf16(acc[2 * bt + 1], al, bh + 2);
            }
            {
                uint32_t bh[2], bl[2];
                ldsm2(bh, base + SO_BHI + b2_off + kofs);
                ldsm2(bl, base + SO_BLO + b2_off + kofs);
                mma_bf16(acc[12], ah, bh);
                mma_bf16(acc[12], ah, bl);
                mma_bf16(acc[12], al, bh);
            }
        }
        __syncthreads();
    }

    // ---- epilogue ----
    int r0 = row0 + wm * 16 + (lane >> 2);
#pragma unroll
    for (int half = 0; half < 2; half++) {
        int gr = r0 + half * 8;
        if (gr >= NN) continue;
        float nv = HAS_AGG ? g_norm[gr] : 0.0f;
#pragma unroll
        for (int nt = 0; nt < 13; nt++) {
            int col = wn * 104 + nt * 8 + ((lane & 3) << 1);
            if (col >= DD) continue;
            float v0 = acc[nt][half * 2 + 0];
            float v1 = acc[nt][half * 2 + 1];
            if (HAS_AGG) {
                float2 ag = *(const float2*)(g_agg + (long)gr * DD + col);
                v0 += ag.x * nv;
                v1 += ag.y * nv;
            }
            float2 bb = *(const float2*)(bias + col);
            v0 = tanhf(v0 + bb.x);
            v1 = tanhf(v1 + bb.y);
            *(float2*)(outf + (long)gr * DD + col) = make_float2(v0, v1);
            if (WRITE_H1) {
                __nv_bfloat16 h0b = __float2bfloat16(v0);
                __nv_bfloat16 h1b = __float2bfloat16(v1);
                __nv_bfloat162 hp; hp.x = h0b; hp.y = h1b;
                __nv_bfloat162 lp;
                lp.x = __float2bfloat16(v0 - __bfloat162float(h0b));
                lp.y = __float2bfloat16(v1 - __bfloat162float(h1b));
                *(__nv_bfloat162*)(h1hi + (long)gr * KP + col) = hp;
                *(__nv_bfloat162*)(h1lo + (long)gr * KP + col) = lp;
            }
        }
    }
}

// ================= launch =================
extern "C" void kernel_launch(void* const* d_in, const int* in_sizes, int n_in,
                              void* d_out, int out_size) {
    const float* node_feat = (const float*)d_in[0];
    const float* dyn       = (const float*)d_in[1];
    const int*   src       = (const int*)d_in[2];
    const int*   dst       = (const int*)d_in[3];
    const int*   et        = (const int*)d_in[4];
    const float* w1        = (const float*)d_in[5];
    const float* lw1       = (const float*)d_in[6];
    const float* b1        = (const float*)d_in[7];
    const float* w2        = (const float*)d_in[8];
    const float* lw2       = (const float*)d_in[9];
    const float* b2        = (const float*)d_in[10];
    const float* Wih       = (const float*)d_in[11];
    const float* Whh       = (const float*)d_in[12];
    const float* bih       = (const float*)d_in[13];
    const float* bhh       = (const float*)d_in[14];
    float* out = (float*)d_out;

    void *agg_p, *norm_p, *h1_p, *bfin_p;
    void *xhi, *xlo, *h1hi, *h1lo, *a2hi, *a2lo, *h0hi, *h0lo;
    void *w1hi, *w1lo, *wihhi, *wihlo, *whhhi, *whhlo, *mthi, *mtlo;
    cudaGetSymbolAddress(&agg_p, g_agg);
    cudaGetSymbolAddress(&norm_p, g_norm);
    cudaGetSymbolAddress(&h1_p, g_h1);
    cudaGetSymbolAddress(&bfin_p, g_bfin);
    cudaGetSymbolAddress(&xhi, g_xhi);     cudaGetSymbolAddress(&xlo, g_xlo);
    cudaGetSymbolAddress(&h1hi, g_h1hi);   cudaGetSymbolAddress(&h1lo, g_h1lo);
    cudaGetSymbolAddress(&a2hi, g_a2hi);   cudaGetSymbolAddress(&a2lo, g_a2lo);
    cudaGetSymbolAddress(&h0hi, g_h0hi);   cudaGetSymbolAddress(&h0lo, g_h0lo);
    cudaGetSymbolAddress(&w1hi, g_w1hi);   cudaGetSymbolAddress(&w1lo, g_w1lo);
    cudaGetSymbolAddress(&wihhi, g_wihhi); cudaGetSymbolAddress(&wihlo, g_wihlo);
    cudaGetSymbolAddress(&whhhi, g_whhhi); cudaGetSymbolAddress(&whhlo, g_whhlo);
    cudaGetSymbolAddress(&mthi, g_mthi);   cudaGetSymbolAddress(&mtlo, g_mtlo);

    cudaFuncSetAttribute(mma_gemm<1, true, true>,
                         cudaFuncAttributeMaxDynamicSharedMemorySize, SM_TOT);
    cudaFuncSetAttribute(mma_gemm<3, false, false>,
                         cudaFuncAttributeMaxDynamicSharedMemorySize, SM_TOT);

    cudaMemsetAsync(agg_p, 0, sizeof(float) * NN * DD);
    cudaMemsetAsync(norm_p, 0, sizeof(float) * NN);

    // one fused prep launch: deg + pack + 3x conv_weight + bmt + bias + padzero + 2x conv_node
    mega_prep<<<MEGA_GRID, 256>>>(node_feat, dyn, src, dst, et,
                                  lw1, Wih, Whh, lw2, b2, bih, bhh);
    norm_kernel<<<(NN + 255) / 256, 256>>>();

    // layer 1
    edge_kernel<<<(EE * 50 + 255) / 256, 256>>>(node_feat, w1);
    mma_gemm<1, true, true><<<NTILES, 256, SM_TOT>>>(
        (const __nv_bfloat16*)xhi, (const __nv_bfloat16*)xlo,
        (const __nv_bfloat16*)w1hi, (const __nv_bfloat16*)w1lo,
        nullptr, nullptr, nullptr, nullptr,
        nullptr, nullptr, nullptr, nullptr,
        b1, (float*)h1_p, (__nv_bfloat16*)h1hi, (__nv_bfloat16*)h1lo);

    // layer 2 scatter + convert
    cudaMemsetAsync(agg_p, 0, sizeof(float) * NN * DD);
    edge_kernel<<<(EE * 50 + 255) / 256, 256>>>((const float*)h1_p, w2);
    conv_node<<<CNB, 256>>>((const float*)agg_p, (__nv_bfloat16*)a2hi,
                            (__nv_bfloat16*)a2lo, 1);

    // fused final: out = tanh( agg2n@Wih^T + h1@(lw2@Wih^T) + h0@Whh^T + bfin )
    mma_gemm<3, false, false><<<NTILES, 256, SM_TOT>>>(
        (const __nv_bfloat16*)a2hi, (const __nv_bfloat16*)a2lo,
        (const __nv_bfloat16*)wihhi, (const __nv_bfloat16*)wihlo,
        (const __nv_bfloat16*)h1hi, (const __nv_bfloat16*)h1lo,
        (const __nv_bfloat16*)mthi, (const __nv_bfloat16*)mtlo,
        (const __nv_bfloat16*)h0hi, (const __nv_bfloat16*)h0lo,
        (const __nv_bfloat16*)whhhi, (const __nv_bfloat16*)whhlo,
        (const float*)bfin_p, out, nullptr, nullptr);
}

// round 16
// speedup vs baseline: 1.7800x; 1.0029x over previous
#include <cuda_runtime.h>
#include <cuda_bf16.h>
#include <math.h>
#include <stdint.h>

#define NN 50000
#define EE 800000
#define DD 200
#define KP 208            // padded K / padded N for weights
#define BM 64             // M tile per CTA (occupancy-2, R14/R15-proven)
#define NTILES ((NN + BM - 1) / BM)   // 782

// smem stage layout (bytes); K-chunk = 32 cols, row stride 80B
#define SO_AHI 0
#define SO_ALO 5120
#define SO_BHI 10240
#define SO_BLO 26880
#define STAGE_BYTES 43520
#define SM_TOT (2 * STAGE_BYTES)      // 87040 per CTA; 2 CTAs/SM

// mega_prep role block counts (256 threads/block)
#define CNB   ((NN * 52 + 255) / 256)   // 10157 conv_node
#define CWB   ((KP * KP + 255) / 256)   // 169 conv_weight
#define BMTB  (13 * 13)                 // 169 bmt tiles
#define PZB   ((NN + 255) / 256)        // 196 padzero
#define DEGB  ((EE + 255) / 256)        // 3125 deg
#define PKB   ((EE + 255) / 256)        // 3125 pack
#define MEGA_GRID (2 * CNB + 3 * CWB + BMTB + 1 + PZB + DEGB + PKB)

// edge layer-1 grid: edge role + norm tail role
#define EB    ((EE * 50) / 256)         // 156250 (exact)
#define NRMB  ((NN + 255) / 256)        // 196

// ================= device scratch =================
__device__ __align__(128) float g_agg[NN * DD];    // layer-1 aggregation
__device__ __align__(128) float g_agg2[NN * DD];   // layer-2 aggregation (double buffer)
__device__ __align__(128) float g_h1[NN * DD];
__device__ __align__(128) float g_norm[NN];        // deg counts -> 1/deg
__device__ __align__(128) float g_bfin[DD];
__device__ __align__(128) unsigned long long g_epk[EE];  // (et<<32)|(dst<<16)|src
__device__ __align__(128) __nv_bfloat16 g_xhi[NN * KP],  g_xlo[NN * KP];
__device__ __align__(128) __nv_bfloat16 g_h1hi[NN * KP], g_h1lo[NN * KP];
__device__ __align__(128) __nv_bfloat16 g_a2hi[NN * KP], g_a2lo[NN * KP];
__device__ __align__(128) __nv_bfloat16 g_h0hi[NN * KP], g_h0lo[NN * KP];
__device__ __align__(128) __nv_bfloat16 g_w1hi[KP * KP],  g_w1lo[KP * KP];
__device__ __align__(128) __nv_bfloat16 g_wihhi[KP * KP], g_wihlo[KP * KP];
__device__ __align__(128) __nv_bfloat16 g_whhhi[KP * KP], g_whhlo[KP * KP];
__device__ __align__(128) __nv_bfloat16 g_mthi[KP * KP],  g_mtlo[KP * KP];

// ================= role bodies =================
__device__ __forceinline__ void conv_node_body(int idx, const float* __restrict__ src,
                                               __nv_bfloat16* __restrict__ hi,
                                               __nv_bfloat16* __restrict__ lo,
                                               bool useNorm) {
    if (idx >= NN * 52) return;
    int n = idx / 52;
    int c4 = idx - n * 52;
    float4 v = make_float4(0.f, 0.f, 0.f, 0.f);
    if (c4 < 50) {
        v = *(const float4*)(src + (long)n * DD + c4 * 4);
        if (useNorm) {
            float nv = g_norm[n];
            v.x *= nv; v.y *= nv; v.z *= nv; v.w *= nv;
        }
    }
    __nv_bfloat16 h0 = __float2bfloat16(v.x);
    __nv_bfloat16 h1 = __float2bfloat16(v.y);
    __nv_bfloat16 h2 = __float2bfloat16(v.z);
    __nv_bfloat16 h3 = __float2bfloat16(v.w);
    __nv_bfloat162 hp0; hp0.x = h0; hp0.y = h1;
    __nv_bfloat162 hp1; hp1.x = h2; hp1.y = h3;
    __nv_bfloat162 lp0;
    lp0.x = __float2bfloat16(v.x - __bfloat162float(h0));
    lp0.y = __float2bfloat16(v.y - __bfloat162float(h1));
    __nv_bfloat162 lp1;
    lp1.x = __float2bfloat16(v.z - __bfloat162float(h2));
    lp1.y = __float2bfloat16(v.w - __bfloat162float(h3));
    long o = (long)n * KP + c4 * 4;
    *(__nv_bfloat162*)(hi + o) = hp0;
    *(__nv_bfloat162*)(hi + o + 2) = hp1;
    *(__nv_bfloat162*)(lo + o) = lp0;
    *(__nv_bfloat162*)(lo + o + 2) = lp1;
}

__device__ __forceinline__ void conv_weight_body(int idx, const float* __restrict__ src,
                                                 __nv_bfloat16* __restrict__ hi,
                                                 __nv_bfloat16* __restrict__ lo,
                                                 bool transpose) {
    if (idx >= KP * KP) return;
    int j = idx / KP;
    int c = idx - j * KP;
    float v = 0.0f;
    if (j < DD && c < DD) v = transpose ? src[c * DD + j] : src[j * DD + c];
    __nv_bfloat16 h = __float2bfloat16(v);
    hi[idx] = h;
    lo[idx] = __float2bfloat16(v - __bfloat162float(h));
}

// ================= mega_prep (R15-proven) =================
__global__ __launch_bounds__(256) void mega_prep(
    const float* __restrict__ x, const float* __restrict__ dyn,
    const int* __restrict__ src, const int* __restrict__ dst,
    const int* __restrict__ et,
    const float* __restrict__ lw1, const float* __restrict__ Wih,
    const float* __restrict__ Whh, const float* __restrict__ lw2,
    const float* __restrict__ b2, const float* __restrict__ bih,
    const float* __restrict__ bhh) {
    __shared__ float sh[544];
    int b = blockIdx.x;
    int tid = threadIdx.x;

    if (b < CNB) {
        conv_node_body(b * 256 + tid, x, g_xhi, g_xlo, false);
        return;
    }
    b -= CNB;
    if (b < CNB) {
        conv_node_body(b * 256 + tid, dyn, g_h0hi, g_h0lo, false);
        return;
    }
    b -= CNB;
    if (b < CWB) {
        conv_weight_body(b * 256 + tid, lw1, g_w1hi, g_w1lo, true);
        return;
    }
    b -= CWB;
    if (b < CWB) {
        conv_weight_body(b * 256 + tid, Wih, g_wihhi, g_wihlo, false);
        return;
    }
    b -= CWB;
    if (b < CWB) {
        conv_weight_body(b * 256 + tid, Whh, g_whhhi, g_whhlo, false);
        return;
    }
    b -= CWB;
    if (b < BMTB) {                      // Mt[j][t] = sum_u Wih[j,u]*lw2[t,u]
        int tj = (b / 13) * 16;
        int tt = (b % 13) * 16;
        float* Ws = sh;
        float* Ls = sh + 272;
        int r = tid >> 4, cth = tid & 15;
        float s = 0.0f;
        for (int kb = 0; kb < DD; kb += 16) {
            int gk = kb + cth;
            int gj = tj + r, gt = tt + r;
            Ws[r * 17 + cth] = (gj < DD && gk < DD) ? Wih[gj * DD + gk] : 0.0f;
            Ls[r * 17 + cth] = (gt < DD && gk < DD) ? lw2[gt * DD + gk] : 0.0f;
            __syncthreads();
#pragma unroll
            for (int u = 0; u < 16; u++) s += Ws[r * 17 + u] * Ls[cth * 17 + u];
            __syncthreads();
        }
        int gj = tj + r, gt = tt + cth;
        if (gj < KP && gt < KP) {
            __nv_bfloat16 h = __float2bfloat16(s);
            g_mthi[gj * KP + gt] = h;
            g_mtlo[gj * KP + gt] = __float2bfloat16(s - __bfloat162float(h));
        }
        return;
    }
    b -= BMTB;
    if (b == 0) {                        // bfin
        for (int i = tid; i < DD; i += 256) sh[i] = b2[i];
        __syncthreads();
        if (tid < DD) {
            float s = bih[tid] + bhh[tid];
#pragma unroll 4
            for (int t = 0; t < DD; t++) s += sh[t] * Wih[tid * DD + t];
            g_bfin[tid] = s;
        }
        return;
    }
    b -= 1;
    if (b < PZB) {                       // padzero h1hi/h1lo
        int idx = b * 256 + tid;
        if (idx < NN) {
            uint4 z = make_uint4(0, 0, 0, 0);
            *(uint4*)(g_h1hi + (long)idx * KP + DD) = z;
            *(uint4*)(g_h1lo + (long)idx * KP + DD) = z;
        }
        return;
    }
    b -= PZB;
    if (b < DEGB) {                      // degree histogram
        int e = b * 256 + tid;
        if (e < EE) atomicAdd(&g_norm[dst[e]], 1.0f);
        return;
    }
    b -= DEGB;
    {                                    // pack edge indices
        int e = b * 256 + tid;
        if (e < EE)
            g_epk[e] = ((unsigned long long)(unsigned)et[e] << 32) |
                       ((unsigned long long)(unsigned)dst[e] << 16) |
                       (unsigned long long)(unsigned)src[e];
    }
}

// ================= edge message + scatter =================
__device__ __forceinline__ void edge_body(int idx, const float* __restrict__ x,
                                          const float* __restrict__ w,
                                          float* __restrict__ agg) {
    int e  = idx / 50;
    int b2 = idx - e * 50;

    unsigned long long pk = __ldg(&g_epk[e]);
    int s = (int)(pk & 0xffff);
    int d = (int)((pk >> 16) & 0xffff);
    int r = (int)(pk >> 32);

    float4 xv = *(const float4*)(x + (long)s * DD + b2 * 4);
    const float4* wp = (const float4*)(w + (long)r * 400 + b2 * 8);
    float4 wA = wp[0];
    float4 wB = wp[1];

    float o0 = xv.x * wA.x + xv.y * wA.z;
    float o1 = xv.x * wA.y + xv.y * wA.w;
    float o2 = xv.z * wB.x + xv.w * wB.z;
    float o3 = xv.z * wB.y + xv.w * wB.w;

    float* ap = agg + (long)d * DD + b2 * 4;
    asm volatile("red.global.add.v4.f32 [%0], {%1, %2, %3, %4};"
                 :: "l"(ap), "f"(o0), "f"(o1), "f"(o2), "f"(o3) : "memory");
}

// layer 1: edge role (blocks < EB) + norm tail role (last NRMB blocks)
__global__ void edge1_kernel(const float* __restrict__ x,
                             const float* __restrict__ w) {
    int b = blockIdx.x;
    if (b < EB) {
        edge_body(b * 256 + threadIdx.x, x, w, g_agg);
    } else {
        int n = (b - EB) * 256 + threadIdx.x;
        if (n < NN) {
            float d = g_norm[n];
            g_norm[n] = (d > 0.0f) ? (1.0f / d) : 0.0f;
        }
    }
}

// layer 2: plain edge, writes g_agg2
__global__ void edge2_kernel(const float* __restrict__ x,
                             const float* __restrict__ w) {
    int idx = blockIdx.x * blockDim.x + threadIdx.x;
    if (idx < EE * 50) edge_body(idx, x, w, g_agg2);
}

// ================= standalone conv (agg2 -> a2hi/lo, normalized) =================
__global__ void conv_node(const float* __restrict__ src,
                          __nv_bfloat16* __restrict__ hi,
                          __nv_bfloat16* __restrict__ lo, int useNorm) {
    conv_node_body(blockIdx.x * 256 + threadIdx.x, src, hi, lo, useNorm != 0);
}

// ================= mma helpers =================
__device__ __forceinline__ uint32_t smem_u32(const void* p) {
    return (uint32_t)__cvta_generic_to_shared(p);
}
__device__ __forceinline__ void ldsm4(uint32_t* r, uint32_t addr) {
    asm volatile("ldmatrix.sync.aligned.m8n8.x4.shared.b16 {%0,%1,%2,%3}, [%4];"
                 : "=r"(r[0]), "=r"(r[1]), "=r"(r[2]), "=r"(r[3]) : "r"(addr));
}
__device__ __forceinline__ void ldsm2(uint32_t* r, uint32_t addr) {
    asm volatile("ldmatrix.sync.aligned.m8n8.x2.shared.b16 {%0,%1}, [%2];"
                 : "=r"(r[0]), "=r"(r[1]) : "r"(addr));
}
__device__ __forceinline__ void mma_bf16(float* c, const uint32_t* a, const uint32_t* b) {
    asm volatile(
        "mma.sync.aligned.m16n8k16.row.col.f32.bf16.bf16.f32 "
        "{%0,%1,%2,%3}, {%4,%5,%6,%7}, {%8,%9}, {%0,%1,%2,%3};"
        : "+f"(c[0]), "+f"(c[1]), "+f"(c[2]), "+f"(c[3])
        : "r"(a[0]), "r"(a[1]), "r"(a[2]), "r"(a[3]), "r"(b[0]), "r"(b[1]));
}
__device__ __forceinline__ void cpa16(uint32_t dsts, const void* src, bool valid) {
    int sz = valid ? 16 : 0;
    asm volatile("cp.async.cg.shared.global [%0], [%1], 16, %2;"
                 :: "r"(dsts), "l"(src), "r"(sz));
}
#define CP_COMMIT() asm volatile("cp.async.commit_group;" ::: "memory")
#define CP_WAIT1()  asm volatile("cp.async.wait_group 1;" ::: "memory")
#define CP_WAIT0()  asm volatile("cp.async.wait_group 0;" ::: "memory")

// ================= occupancy-2 3-term MMA GEMM (R14/R15-proven, unchanged) =================
template <int NPASS, bool HAS_AGG, bool WRITE_H1>
__global__ void __launch_bounds__(256, 2) mma_gemm(
    const __nv_bfloat16* __restrict__ A0h, const __nv_bfloat16* __restrict__ A0l,
    const __nv_bfloat16* __restrict__ B0h, const __nv_bfloat16* __restrict__ B0l,
    const __nv_bfloat16* __restrict__ A1h, const __nv_bfloat16* __restrict__ A1l,
    const __nv_bfloat16* __restrict__ B1h, const __nv_bfloat16* __restrict__ B1l,
    const __nv_bfloat16* __restrict__ A2h, const __nv_bfloat16* __restrict__ A2l,
    const __nv_bfloat16* __restrict__ B2h, const __nv_bfloat16* __restrict__ B2l,
    const float* __restrict__ bias, float* __restrict__ outf,
    __nv_bfloat16* __restrict__ h1hi, __nv_bfloat16* __restrict__ h1lo) {
    extern __shared__ __align__(128) char smem[];
    uint32_t sb = smem_u32(smem);

    int tid = threadIdx.x;
    int lane = tid & 31;
    int wid = tid >> 5;
    int wm = wid & 3;
    int wn = wid >> 2;
    int row0 = blockIdx.x * BM;

    float acc[13][4];
#pragma unroll
    for (int nt = 0; nt < 13; nt++)
#pragma unroll
        for (int q = 0; q < 4; q++) acc[nt][q] = 0.0f;

    const __nv_bfloat16* Ahp[3] = {A0h, A1h, A2h};
    const __nv_bfloat16* Alp[3] = {A0l, A1l, A2l};
    const __nv_bfloat16* Bhp[3] = {B0h, B1h, B2h};
    const __nv_bfloat16* Blp[3] = {B0l, B1l, B2l};

    const int total = NPASS * 7;

    auto load_chunk = [&](int t, int stage) {
        int p = t / 7, c = t - p * 7;
        int kb = c * 32;
        int sh = (c == 6) ? 1 : 2;
        int msk = (1 << sh) - 1;
        uint32_t base = sb + stage * STAGE_BYTES;
        const __nv_bfloat16* Ah = Ahp[p];
        const __nv_bfloat16* Al = Alp[p];
        const __nv_bfloat16* Bh = Bhp[p];
        const __nv_bfloat16* Bl = Blp[p];
        int nA = 64 << sh;
        for (int i = tid; i < nA; i += 256) {
            int r = i >> sh, u = i & msk;
            int gr = row0 + r;
            bool v = gr < NN;
            long off = (long)gr * KP + kb + u * 8;
            cpa16(base + SO_AHI + r * 80 + u * 16, Ah + off, v);
            cpa16(base + SO_ALO + r * 80 + u * 16, Al + off, v);
        }
        int nB = 208 << sh;
        for (int i = tid; i < nB; i += 256) {
            int r = i >> sh, u = i & msk;
            long off = (long)r * KP + kb + u * 8;
            cpa16(base + SO_BHI + r * 80 + u * 16, Bh + off, true);
            cpa16(base + SO_BLO + r * 80 + u * 16, Bl + off, true);
        }
        CP_COMMIT();
    };

    uint32_t a_off = (uint32_t)((wm * 16 + (lane & 15)) * 80 + (((lane >> 4) << 3) << 1));
    uint32_t b_off = (uint32_t)((wn * 104 + (lane & 7) + ((lane >> 4) << 3)) * 80 +
                                ((((lane >> 3) & 1) << 3) << 1));
    uint32_t b2_off = (uint32_t)((wn * 104 + 96 + (lane & 7)) * 80 +
                                 ((((lane >> 3) & 1) << 3) << 1));

    load_chunk(0, 0);

#pragma unroll 1
    for (int t = 0; t < total; t++) {
        if (t + 1 < total) {
            load_chunk(t + 1, (t + 1) & 1);
            CP_WAIT1();
        } else {
            CP_WAIT0();
        }
        __syncthreads();

        int c = t - (t / 7) * 7;
        int nk16 = (c == 6) ? 1 : 2;
        uint32_t base = sb + (t & 1) * STAGE_BYTES;
#pragma unroll
        for (int k16 = 0; k16 < 2; k16++) {
            if (k16 >= nk16) break;
            uint32_t kofs = (uint32_t)(k16 << 5);
            uint32_t ah[4], al[4];
            ldsm4(ah, base + SO_AHI + a_off + kofs);
            ldsm4(al, base + SO_ALO + a_off + kofs);
#pragma unroll
            for (int bt = 0; bt < 6; bt++) {
                uint32_t bh[4], bl[4];
                ldsm4(bh, base + SO_BHI + b_off + bt * (16 * 80) + kofs);
                ldsm4(bl, base + SO_BLO + b_off + bt * (16 * 80) + kofs);
                mma_bf16(acc[2 * bt],     ah, bh);
                mma_bf16(acc[2 * bt + 1], ah, bh + 2);
                mma_bf16(acc[2 * bt],     ah, bl);
                mma_bf16(acc[2 * bt + 1], ah, bl + 2);
                mma_bf16(acc[2 * bt],     al, bh);
                mma_bf16(acc[2 * bt + 1], al, bh + 2);
            }
            {
                uint32_t bh[2], bl[2];
                ldsm2(bh, base + SO_BHI + b2_off + kofs);
                ldsm2(bl, base + SO_BLO + b2_off + kofs);
                mma_bf16(acc[12], ah, bh);
                mma_bf16(acc[12], ah, bl);
                mma_bf16(acc[12], al, bh);
            }
        }
        __syncthreads();
    }

    // ---- epilogue ----
    int r0 = row0 + wm * 16 + (lane >> 2);
#pragma unroll
    for (int half = 0; half < 2; half++) {
        int gr = r0 + half * 8;
        if (gr >= NN) continue;
        float nv = HAS_AGG ? g_norm[gr] : 0.0f;
#pragma unroll
        for (int nt = 0; nt < 13; nt++) {
            int col = wn * 104 + nt * 8 + ((lane & 3) << 1);
            if (col >= DD) continue;
            float v0 = acc[nt][half * 2 + 0];
            float v1 = acc[nt][half * 2 + 1];
            if (HAS_AGG) {
                float2 ag = *(const float2*)(g_agg + (long)gr * DD + col);
                v0 += ag.x * nv;
                v1 += ag.y * nv;
            }
            float2 bb = *(const float2*)(bias + col);
            v0 = tanhf(v0 + bb.x);
            v1 = tanhf(v1 + bb.y);
            *(float2*)(outf + (long)gr * DD + col) = make_float2(v0, v1);
            if (WRITE_H1) {
                __nv_bfloat16 h0b = __float2bfloat16(v0);
                __nv_bfloat16 h1b = __float2bfloat16(v1);
                __nv_bfloat162 hp; hp.x = h0b; hp.y = h1b;
                __nv_bfloat162 lp;
                lp.x = __float2bfloat16(v0 - __bfloat162float(h0b));
                lp.y = __float2bfloat16(v1 - __bfloat162float(h1b));
                *(__nv_bfloat162*)(h1hi + (long)gr * KP + col) = hp;
                *(__nv_bfloat162*)(h1lo + (long)gr * KP + col) = lp;
            }
        }
    }
}

// ================= launch =================
extern "C" void kernel_launch(void* const* d_in, const int* in_sizes, int n_in,
                              void* d_out, int out_size) {
    const float* node_feat = (const float*)d_in[0];
    const float* dyn       = (const float*)d_in[1];
    const int*   src       = (const int*)d_in[2];
    const int*   dst       = (const int*)d_in[3];
    const int*   et        = (const int*)d_in[4];
    const float* w1        = (const float*)d_in[5];
    const float* lw1       = (const float*)d_in[6];
    const float* b1        = (const float*)d_in[7];
    const float* w2        = (const float*)d_in[8];
    const float* lw2       = (const float*)d_in[9];
    const float* b2        = (const float*)d_in[10];
    const float* Wih       = (const float*)d_in[11];
    const float* Whh       = (const float*)d_in[12];
    const float* bih       = (const float*)d_in[13];
    const float* bhh       = (const float*)d_in[14];
    float* out = (float*)d_out;

    void *agg_p, *agg2_p, *norm_p, *h1_p, *bfin_p;
    void *xhi, *xlo, *h1hi, *h1lo, *a2hi, *a2lo, *h0hi, *h0lo;
    void *w1hi, *w1lo, *wihhi, *wihlo, *whhhi, *whhlo, *mthi, *mtlo;
    cudaGetSymbolAddress(&agg_p, g_agg);
    cudaGetSymbolAddress(&agg2_p, g_agg2);
    cudaGetSymbolAddress(&norm_p, g_norm);
    cudaGetSymbolAddress(&h1_p, g_h1);
    cudaGetSymbolAddress(&bfin_p, g_bfin);
    cudaGetSymbolAddress(&xhi, g_xhi);     cudaGetSymbolAddress(&xlo, g_xlo);
    cudaGetSymbolAddress(&h1hi, g_h1hi);   cudaGetSymbolAddress(&h1lo, g_h1lo);
    cudaGetSymbolAddress(&a2hi, g_a2hi);   cudaGetSymbolAddress(&a2lo, g_a2lo);
    cudaGetSymbolAddress(&h0hi, g_h0hi);   cudaGetSymbolAddress(&h0lo, g_h0lo);
    cudaGetSymbolAddress(&w1hi, g_w1hi);   cudaGetSymbolAddress(&w1lo, g_w1lo);
    cudaGetSymbolAddress(&wihhi, g_wihhi); cudaGetSymbolAddress(&wihlo, g_wihlo);
    cudaGetSymbolAddress(&whhhi, g_whhhi); cudaGetSymbolAddress(&whhlo, g_whhlo);
    cudaGetSymbolAddress(&mthi, g_mthi);   cudaGetSymbolAddress(&mtlo, g_mtlo);

    cudaFuncSetAttribute(mma_gemm<1, true, true>,
                         cudaFuncAttributeMaxDynamicSharedMemorySize, SM_TOT);
    cudaFuncSetAttribute(mma_gemm<3, false, false>,
                         cudaFuncAttributeMaxDynamicSharedMemorySize, SM_TOT);

    // all memsets upfront (agg2 double-buffer removes the mid-pipeline memset)
    cudaMemsetAsync(agg_p, 0, sizeof(float) * NN * DD);
    cudaMemsetAsync(agg2_p, 0, sizeof(float) * NN * DD);
    cudaMemsetAsync(norm_p, 0, sizeof(float) * NN);

    // fused prep: deg + pack + 3x conv_weight + bmt + bias + padzero + 2x conv_node
    mega_prep<<<MEGA_GRID, 256>>>(node_feat, dyn, src, dst, et,
                                  lw1, Wih, Whh, lw2, b2, bih, bhh);

    // layer 1: edge scatter + norm-invert tail role
    edge1_kernel<<<EB + NRMB, 256>>>(node_feat, w1);
    mma_gemm<1, true, true><<<NTILES, 256, SM_TOT>>>(
        (const __nv_bfloat16*)xhi, (const __nv_bfloat16*)xlo,
        (const __nv_bfloat16*)w1hi, (const __nv_bfloat16*)w1lo,
        nullptr, nullptr, nullptr, nullptr,
        nullptr, nullptr, nullptr, nullptr,
        b1, (float*)h1_p, (__nv_bfloat16*)h1hi, (__nv_bfloat16*)h1lo);

    // layer 2: scatter into pre-zeroed g_agg2, then convert
    edge2_kernel<<<EB, 256>>>((const float*)h1_p, w2);
    conv_node<<<CNB, 256>>>((const float*)agg2_p, (__nv_bfloat16*)a2hi,
                            (__nv_bfloat16*)a2lo, 1);

    // fused final: out = tanh( agg2n@Wih^T + h1@(lw2@Wih^T) + h0@Whh^T + bfin )
    mma_gemm<3, false, false><<<NTILES, 256, SM_TOT>>>(
        (const __nv_bfloat16*)a2hi, (const __nv_bfloat16*)a2lo,
        (const __nv_bfloat16*)wihhi, (const __nv_bfloat16*)wihlo,
        (const __nv_bfloat16*)h1hi, (const __nv_bfloat16*)h1lo,
        (const __nv_bfloat16*)mthi, (const __nv_bfloat16*)mtlo,
        (const __nv_bfloat16*)h0hi, (const __nv_bfloat16*)h0lo,
        (const __nv_bfloat16*)whhhi, (const __nv_bfloat16*)whhlo,
        (const float*)bfin_p, out, nullptr, nullptr);
}